// round 5
// baseline (speedup 1.0000x reference)
#include <cuda_runtime.h>
#include <math.h>

// ---------------- static scratch (no allocations allowed) ----------------
__device__ float g_bufA[8520192];
__device__ float g_bufB[8520192];
__device__ float g_bufC[1843200];   // partial-sum buffers for K-split convs
__device__ float g_bufD[1843200];
__device__ float g_cnorm[512];
__device__ float g_partial[256];

#define LRELU_SLOPE 0.01f

// ================= conv2d: 2D register tile (SPT spatial x CT channels) ======
template<int CIN, int COUT, int CT, int K, int S, int P, int SPT, int ACT>
__global__ void __launch_bounds__(128)
conv_t2(const float* __restrict__ in, const float* __restrict__ w,
        const float* __restrict__ bias, float* __restrict__ out,
        int HIN, int WIN, int HOUT, int WOUT, int GW)
{
    const int cob = blockIdx.y * CT;
    const int nb  = blockIdx.z;

    __shared__ __align__(16) float sw[CIN * K * K * CT];
    __shared__ float sb[CT];
    for (int i = threadIdx.x; i < CIN * K * K * CT; i += blockDim.x) {
        int tap = i / CT, co = i - tap * CT;
        sw[i] = w[(size_t)(cob + co) * CIN * K * K + tap];
    }
    if (threadIdx.x < CT) sb[threadIdx.x] = bias[cob + threadIdx.x];
    __syncthreads();

    int g = blockIdx.x * blockDim.x + threadIdx.x;
    if (g >= HOUT * GW) return;
    int oh  = g / GW;
    int ow0 = (g - oh * GW) * SPT;

    const float* ib = in + (size_t)nb * CIN * HIN * WIN;

    float acc[SPT][CT];
    #pragma unroll
    for (int s = 0; s < SPT; s++)
        #pragma unroll
        for (int c = 0; c < CT; c++) acc[s][c] = sb[c];

    constexpr int NIW = (SPT - 1) * S + K;
    const int iwb = ow0 * S - P;

    #pragma unroll 2
    for (int ci = 0; ci < CIN; ci++) {
        #pragma unroll
        for (int kh = 0; kh < K; kh++) {
            int ih = oh * S - P + kh;
            bool rv = ((unsigned)ih < (unsigned)HIN);
            const float* rp = ib + ((size_t)ci * HIN + ih) * WIN;
            float inv[NIW];
            #pragma unroll
            for (int j = 0; j < NIW; j++) {
                int iw = iwb + j;
                inv[j] = (rv && iw >= 0 && iw < WIN) ? rp[iw] : 0.f;
            }
            #pragma unroll
            for (int kw = 0; kw < K; kw++) {
                #pragma unroll
                for (int c4 = 0; c4 < CT / 4; c4++) {
                    float4 wv = *(const float4*)&sw[((ci * K + kh) * K + kw) * CT + c4 * 4];
                    #pragma unroll
                    for (int s = 0; s < SPT; s++) {
                        float v = inv[s * S + kw];
                        acc[s][c4*4+0] = fmaf(v, wv.x, acc[s][c4*4+0]);
                        acc[s][c4*4+1] = fmaf(v, wv.y, acc[s][c4*4+1]);
                        acc[s][c4*4+2] = fmaf(v, wv.z, acc[s][c4*4+2]);
                        acc[s][c4*4+3] = fmaf(v, wv.w, acc[s][c4*4+3]);
                    }
                }
            }
        }
    }

    #pragma unroll
    for (int s = 0; s < SPT; s++) {
        int ow = ow0 + s;
        if (ow >= WOUT) continue;
        #pragma unroll
        for (int c = 0; c < CT; c++) {
            float a = acc[s][c];
            if (ACT == 1) a = a >= 0.f ? a : LRELU_SLOPE * a;
            out[(((size_t)nb * COUT + cob + c) * HOUT + oh) * WOUT + ow] = a;
        }
    }
}

// ===== conv2d partial (K-split over CIN halves): raw partial sums, no bias/act =====
// blockIdx.y = cihalf * (COUT/CT) + cotile. Half 0 -> out0, half 1 -> out1.
template<int CIN, int CIHALF, int COUT, int CT, int K, int S, int P, int SPT>
__global__ void __launch_bounds__(128)
conv_part(const float* __restrict__ in, const float* __restrict__ w,
          float* __restrict__ out0, float* __restrict__ out1,
          int HIN, int WIN, int HOUT, int WOUT, int GW)
{
    constexpr int NT = COUT / CT;
    const int cihalf = blockIdx.y / NT;
    const int cob = (blockIdx.y - cihalf * NT) * CT;
    const int cib = cihalf * CIHALF;
    const int nb  = blockIdx.z;
    float* outp = cihalf ? out1 : out0;

    __shared__ __align__(16) float sw[CIHALF * K * K * CT];
    for (int i = threadIdx.x; i < CIHALF * K * K * CT; i += blockDim.x) {
        int tap = i / CT, co = i - tap * CT;
        int cil = tap / (K * K), r = tap - cil * K * K;
        sw[i] = w[((size_t)(cob + co) * CIN + cib + cil) * K * K + r];
    }
    __syncthreads();

    int g = blockIdx.x * blockDim.x + threadIdx.x;
    if (g >= HOUT * GW) return;
    int oh  = g / GW;
    int ow0 = (g - oh * GW) * SPT;

    const float* ib = in + ((size_t)nb * CIN + cib) * HIN * WIN;

    float acc[SPT][CT];
    #pragma unroll
    for (int s = 0; s < SPT; s++)
        #pragma unroll
        for (int c = 0; c < CT; c++) acc[s][c] = 0.f;

    constexpr int NIW = (SPT - 1) * S + K;
    const int iwb = ow0 * S - P;

    #pragma unroll 2
    for (int ci = 0; ci < CIHALF; ci++) {
        #pragma unroll
        for (int kh = 0; kh < K; kh++) {
            int ih = oh * S - P + kh;
            bool rv = ((unsigned)ih < (unsigned)HIN);
            const float* rp = ib + ((size_t)ci * HIN + ih) * WIN;
            float inv[NIW];
            #pragma unroll
            for (int j = 0; j < NIW; j++) {
                int iw = iwb + j;
                inv[j] = (rv && iw >= 0 && iw < WIN) ? rp[iw] : 0.f;
            }
            #pragma unroll
            for (int kw = 0; kw < K; kw++) {
                #pragma unroll
                for (int c4 = 0; c4 < CT / 4; c4++) {
                    float4 wv = *(const float4*)&sw[((ci * K + kh) * K + kw) * CT + c4 * 4];
                    #pragma unroll
                    for (int s = 0; s < SPT; s++) {
                        float v = inv[s * S + kw];
                        acc[s][c4*4+0] = fmaf(v, wv.x, acc[s][c4*4+0]);
                        acc[s][c4*4+1] = fmaf(v, wv.y, acc[s][c4*4+1]);
                        acc[s][c4*4+2] = fmaf(v, wv.z, acc[s][c4*4+2]);
                        acc[s][c4*4+3] = fmaf(v, wv.w, acc[s][c4*4+3]);
                    }
                }
            }
        }
    }

    #pragma unroll
    for (int s = 0; s < SPT; s++) {
        int ow = ow0 + s;
        if (ow >= WOUT) continue;
        #pragma unroll
        for (int c = 0; c < CT; c++)
            outp[(((size_t)nb * COUT + cob + c) * HOUT + oh) * WOUT + ow] = acc[s][c];
    }
}

// ----- fuse: out = lrelu(p0 + p1 + bias[c]) for [B, C, HW] layout -----
__global__ void fuse_add_lrelu(const float* __restrict__ p0, const float* __restrict__ p1,
                               const float* __restrict__ bias, float* __restrict__ out,
                               int HW, int C, int total)
{
    int i = blockIdx.x * 256 + threadIdx.x;
    if (i >= total) return;
    int c = (i / HW) % C;
    float a = p0[i] + p1[i] + bias[c];
    out[i] = a >= 0.f ? a : LRELU_SLOPE * a;
}

// ============ transposed conv k=4 s=2 (gather), 2D register tile ============
template<int CIN, int COUT, int CT, int SPT, int ACT>
__global__ void __launch_bounds__(128)
tconv_t2(const float* __restrict__ in, const float* __restrict__ w,
         const float* __restrict__ bias, float* __restrict__ out,
         int HIN, int WIN, int HOUT, int WOUT, int GW)
{
    const int cob = blockIdx.y * CT;
    const int nb  = blockIdx.z;

    __shared__ __align__(16) float sw[CIN * 16 * CT];
    __shared__ float sb[CT];
    for (int i = threadIdx.x; i < CIN * 16 * CT; i += blockDim.x) {
        int ci = i / (16 * CT);
        int r  = i - ci * 16 * CT;
        int tap = r / CT, co = r - tap * CT;
        sw[i] = w[((size_t)ci * COUT + cob + co) * 16 + tap];
    }
    if (threadIdx.x < CT) sb[threadIdx.x] = bias[cob + threadIdx.x];
    __syncthreads();

    int g = blockIdx.x * blockDim.x + threadIdx.x;
    if (g >= HOUT * GW) return;
    int oh  = g / GW;
    int ow0 = (g - oh * GW) * SPT;
    const int hpar = oh & 1;

    const float* ib = in + (size_t)nb * CIN * HIN * WIN;

    float acc[SPT][CT];
    #pragma unroll
    for (int s = 0; s < SPT; s++)
        #pragma unroll
        for (int c = 0; c < CT; c++) acc[s][c] = sb[c];

    constexpr int NIW = SPT / 2 + 1;
    const int iwb = (ow0 >> 1) - 1;

    #pragma unroll 2
    for (int ci = 0; ci < CIN; ci++) {
        #pragma unroll
        for (int dkh = 0; dkh < 2; dkh++) {
            int kh = hpar + 2 * dkh;
            int t  = oh - kh;
            int ih = t >> 1;
            bool rv = (t >= 0) && (ih < HIN);
            const float* rp = ib + ((size_t)ci * HIN + ih) * WIN;
            float inv[NIW];
            #pragma unroll
            for (int j = 0; j < NIW; j++) {
                int iw = iwb + j;
                inv[j] = (rv && iw >= 0 && iw < WIN) ? rp[iw] : 0.f;
            }
            #pragma unroll
            for (int dkw = 0; dkw < 2; dkw++) {
                #pragma unroll
                for (int wpar = 0; wpar < 2; wpar++) {
                    int tap = kh * 4 + wpar + 2 * dkw;
                    if (CT >= 4) {
                        #pragma unroll
                        for (int c4 = 0; c4 < CT / 4; c4++) {
                            float4 wv = *(const float4*)&sw[(ci * 16 + tap) * CT + c4 * 4];
                            #pragma unroll
                            for (int s = wpar; s < SPT; s += 2) {
                                float v = inv[s / 2 + 1 - dkw];
                                acc[s][c4*4+0] = fmaf(v, wv.x, acc[s][c4*4+0]);
                                acc[s][c4*4+1] = fmaf(v, wv.y, acc[s][c4*4+1]);
                                acc[s][c4*4+2] = fmaf(v, wv.z, acc[s][c4*4+2]);
                                acc[s][c4*4+3] = fmaf(v, wv.w, acc[s][c4*4+3]);
                            }
                        }
                    } else {
                        #pragma unroll
                        for (int c = 0; c < CT; c++) {
                            float wa = sw[(ci * 16 + tap) * CT + c];
                            #pragma unroll
                            for (int s = wpar; s < SPT; s += 2)
                                acc[s][c] = fmaf(inv[s / 2 + 1 - dkw], wa, acc[s][c]);
                        }
                    }
                }
            }
        }
    }

    #pragma unroll
    for (int s = 0; s < SPT; s++) {
        int ow = ow0 + s;
        if (ow >= WOUT) continue;
        #pragma unroll
        for (int c = 0; c < CT; c++) {
            float a = acc[s][c];
            if (ACT == 1) a = a >= 0.f ? a : LRELU_SLOPE * a;
            if (ACT == 2) a = tanhf(a);
            out[(((size_t)nb * COUT + cob + c) * HOUT + oh) * WOUT + ow] = a;
        }
    }
}

// ---------------- codebook squared norms ----------------
__global__ void cnorm_k(const float* __restrict__ cb)
{
    int c = blockIdx.x * blockDim.x + threadIdx.x;
    if (c < 512) {
        float s = 0.f;
        #pragma unroll
        for (int d = 0; d < 64; d++) {
            float v = cb[c * 64 + d];
            s = fmaf(v, v, s);
        }
        g_cnorm[c] = s;
    }
}

// --------- VQ: 2 positions/thread, argmax(dot - 0.5*||c||^2) -----------
// 28800 threads = 225 blocks x 128; thread handles pos gid and gid+28800.
__global__ void __launch_bounds__(128) vq2_k(const float* __restrict__ e5,
                                             const float* __restrict__ cb,
                                             float* __restrict__ z)
{
    __shared__ __align__(16) float scb[128 * 64];
    __shared__ float scn[128];
    __shared__ float red[128];

    const int gid = blockIdx.x * 128 + threadIdx.x;
    const int n0 = gid, n1 = gid + 28800;
    const int b0 = n0 / 900, sp0 = n0 - b0 * 900;
    const int b1 = n1 / 900, sp1 = n1 - b1 * 900;

    float lat0[64], lat1[64];
    float fn0 = 0.f, fn1 = 0.f;
    #pragma unroll
    for (int d = 0; d < 64; d++) {
        float v0 = e5[((size_t)(b0 * 64 + d)) * 900 + sp0];
        float v1 = e5[((size_t)(b1 * 64 + d)) * 900 + sp1];
        lat0[d] = v0; lat1[d] = v1;
        fn0 = fmaf(v0, v0, fn0);
        fn1 = fmaf(v1, v1, fn1);
    }

    float best0 = -1e30f, best1 = -1e30f;
    int bi0 = 0, bi1 = 0;
    for (int cbase = 0; cbase < 512; cbase += 128) {
        const float4* src = (const float4*)(cb + cbase * 64);
        float4* dst = (float4*)scb;
        for (int i = threadIdx.x; i < 2048; i += 128) dst[i] = src[i];
        if (threadIdx.x < 128) scn[threadIdx.x] = g_cnorm[cbase + threadIdx.x];
        __syncthreads();

        for (int c = 0; c < 128; c++) {
            const float4* cp = (const float4*)&scb[c * 64];
            float a0 = 0.f, a1 = 0.f, b0a = 0.f, b1a = 0.f;
            #pragma unroll
            for (int q = 0; q < 16; q += 2) {
                float4 w0 = cp[q], w1 = cp[q + 1];
                a0 = fmaf(lat0[4*q+0], w0.x, a0); a0 = fmaf(lat0[4*q+1], w0.y, a0);
                a0 = fmaf(lat0[4*q+2], w0.z, a0); a0 = fmaf(lat0[4*q+3], w0.w, a0);
                b0a = fmaf(lat0[4*q+4], w1.x, b0a); b0a = fmaf(lat0[4*q+5], w1.y, b0a);
                b0a = fmaf(lat0[4*q+6], w1.z, b0a); b0a = fmaf(lat0[4*q+7], w1.w, b0a);
                a1 = fmaf(lat1[4*q+0], w0.x, a1); a1 = fmaf(lat1[4*q+1], w0.y, a1);
                a1 = fmaf(lat1[4*q+2], w0.z, a1); a1 = fmaf(lat1[4*q+3], w0.w, a1);
                b1a = fmaf(lat1[4*q+4], w1.x, b1a); b1a = fmaf(lat1[4*q+5], w1.y, b1a);
                b1a = fmaf(lat1[4*q+6], w1.z, b1a); b1a = fmaf(lat1[4*q+7], w1.w, b1a);
            }
            float hn = 0.5f * scn[c];
            float s0 = a0 + b0a - hn;
            float s1 = a1 + b1a - hn;
            if (s0 > best0) { best0 = s0; bi0 = cbase + c; }
            if (s1 > best1) { best1 = s1; bi1 = cbase + c; }
        }
        __syncthreads();
    }

    const float* cq0 = cb + bi0 * 64;
    const float* cq1 = cb + bi1 * 64;
    #pragma unroll
    for (int d = 0; d < 64; d++) {
        z[((size_t)(b0 * 64 + d)) * 900 + sp0] = cq0[d];
        z[((size_t)(b1 * 64 + d)) * 900 + sp1] = cq1[d];
    }

    red[threadIdx.x] = (fn0 - 2.f * best0) + (fn1 - 2.f * best1);
    __syncthreads();
    for (int s = 64; s > 0; s >>= 1) {
        if (threadIdx.x < s) red[threadIdx.x] += red[threadIdx.x + s];
        __syncthreads();
    }
    if (threadIdx.x == 0) g_partial[blockIdx.x] = red[0];
}

// ---------------- deterministic loss finalize ----------------
__global__ void loss_fin(float* __restrict__ out, int out_size)
{
    __shared__ float red[256];
    float v = (threadIdx.x < 225) ? g_partial[threadIdx.x] : 0.f;
    red[threadIdx.x] = v;
    __syncthreads();
    for (int s = 128; s > 0; s >>= 1) {
        if (threadIdx.x < s) red[threadIdx.x] += red[threadIdx.x + s];
        __syncthreads();
    }
    if (threadIdx.x == 0)
        out[out_size - 1] = 1.25f * red[0] / 3686400.0f;
}

// ---------------- launch ----------------
extern "C" void kernel_launch(void* const* d_in, const int* in_sizes, int n_in,
                              void* d_out, int out_size)
{
    (void)in_sizes; (void)n_in;
    const float* x   = (const float*)d_in[0];
    const float* ew1 = (const float*)d_in[1];  const float* eb1 = (const float*)d_in[2];
    const float* ew2 = (const float*)d_in[3];  const float* eb2 = (const float*)d_in[4];
    const float* ew3 = (const float*)d_in[5];  const float* eb3 = (const float*)d_in[6];
    const float* ew4 = (const float*)d_in[7];  const float* eb4 = (const float*)d_in[8];
    const float* ew5 = (const float*)d_in[9];  const float* eb5 = (const float*)d_in[10];
    const float* dw1 = (const float*)d_in[11]; const float* db1 = (const float*)d_in[12];
    const float* dw2 = (const float*)d_in[13]; const float* db2 = (const float*)d_in[14];
    const float* dw3 = (const float*)d_in[15]; const float* db3 = (const float*)d_in[16];
    const float* dw4 = (const float*)d_in[17]; const float* db4 = (const float*)d_in[18];
    const float* cbk = (const float*)d_in[19];
    float* out = (float*)d_out;

    float *bufA, *bufB, *bufC, *bufD;
    cudaGetSymbolAddress((void**)&bufA, g_bufA);
    cudaGetSymbolAddress((void**)&bufB, g_bufB);
    cudaGetSymbolAddress((void**)&bufC, g_bufC);
    cudaGetSymbolAddress((void**)&bufD, g_bufD);

    const int B = 64;

    // ---- encoder ----
    // conv1: [64,1,256,256] -> [64,8,127,127]  SPT=4 CT=8
    conv_t2<1, 8, 8, 4, 2, 0, 4, 1><<<dim3(32, 1, B), 128>>>(x, ew1, eb1, bufA, 256, 256, 127, 127, 32);
    // conv2: -> [64,16,62,62]  SPT=2 CT=16
    conv_t2<8, 16, 16, 4, 2, 0, 2, 1><<<dim3(16, 1, B), 128>>>(bufA, ew2, eb2, bufB, 127, 127, 62, 62, 31);
    // conv3: -> [64,32,30,30]  SPT=5 CT=8 (R3 config), block 96, GW=6
    conv_t2<16, 32, 8, 4, 2, 0, 5, 1><<<dim3(2, 4, B), 96>>>(bufB, ew3, eb3, bufA, 62, 62, 30, 30, 6);
    // conv4 K-split: 2 halves of CIN=32, SPT=5 -> partials C,D; fuse -> bufB
    conv_part<32, 16, 32, 8, 3, 1, 1, 5><<<dim3(2, 8, B), 96>>>(bufA, ew4, bufC, bufD, 30, 30, 30, 30, 6);
    fuse_add_lrelu<<<(1843200 + 255) / 256, 256>>>(bufC, bufD, eb4, bufB, 900, 32, 1843200);
    // conv5: 1x1 -> [64,64,30,30]  SPT=4 CT=16
    conv_t2<32, 64, 16, 1, 1, 0, 4, 1><<<dim3(2, 4, B), 128>>>(bufB, ew5, eb5, bufA, 30, 30, 30, 30, 8);

    // ---- VQ ----
    cnorm_k<<<2, 256>>>(cbk);
    vq2_k<<<225, 128>>>(bufA, cbk, bufB);

    // ---- decoder ----
    // d1 K-split: 2 halves of CIN=64, SPT=5 -> partials C,D; fuse -> bufA
    conv_part<64, 32, 32, 8, 3, 1, 1, 5><<<dim3(2, 8, B), 96>>>(bufB, dw1, bufC, bufD, 30, 30, 30, 30, 6);
    fuse_add_lrelu<<<(1843200 + 255) / 256, 256>>>(bufC, bufD, db1, bufA, 900, 32, 1843200);
    // t2: 32->16, 30 -> 63  SPT=4 CT=8 y=2
    tconv_t2<32, 16, 8, 4, 1><<<dim3(8, 2, B), 128>>>(bufA, dw2, db2, bufB, 30, 30, 63, 63, 16);
    // t3: 16->8, 63 -> 129  SPT=4 CT=8
    tconv_t2<16, 8, 8, 4, 1><<<dim3(34, 1, B), 128>>>(bufB, dw3, db3, bufA, 63, 63, 129, 129, 33);
    // t4: 8->1, 129 -> 260, tanh  SPT=8 CT=1
    tconv_t2<8, 1, 1, 8, 2><<<dim3(68, 1, B), 128>>>(bufA, dw4, db4, out, 129, 129, 260, 260, 33);

    // ---- loss scalar ----
    loss_fin<<<1, 256>>>(out, out_size);
}

// round 6
// speedup vs baseline: 1.1337x; 1.1337x over previous
#include <cuda_runtime.h>
#include <math.h>
#include <stdint.h>

// ---------------- static scratch (no allocations allowed) ----------------
__device__ float g_bufA[8520192];
__device__ float g_bufB[8520192];
__device__ float g_wT[18432];      // d1 weights, tf32, layout [tap][ci][co]
__device__ float g_cnorm[512];
__device__ float g_partial[256];

#define LRELU_SLOPE 0.01f

// ================= conv2d: 2D register tile (SPT spatial x CT channels) ======
template<int CIN, int COUT, int CT, int K, int S, int P, int SPT, int ACT>
__global__ void __launch_bounds__(128)
conv_t2(const float* __restrict__ in, const float* __restrict__ w,
        const float* __restrict__ bias, float* __restrict__ out,
        int HIN, int WIN, int HOUT, int WOUT, int GW)
{
    const int cob = blockIdx.y * CT;
    const int nb  = blockIdx.z;

    __shared__ __align__(16) float sw[CIN * K * K * CT];
    __shared__ float sb[CT];
    for (int i = threadIdx.x; i < CIN * K * K * CT; i += blockDim.x) {
        int tap = i / CT, co = i - tap * CT;
        sw[i] = w[(size_t)(cob + co) * CIN * K * K + tap];
    }
    if (threadIdx.x < CT) sb[threadIdx.x] = bias[cob + threadIdx.x];
    __syncthreads();

    int g = blockIdx.x * blockDim.x + threadIdx.x;
    if (g >= HOUT * GW) return;
    int oh  = g / GW;
    int ow0 = (g - oh * GW) * SPT;

    const float* ib = in + (size_t)nb * CIN * HIN * WIN;

    float acc[SPT][CT];
    #pragma unroll
    for (int s = 0; s < SPT; s++)
        #pragma unroll
        for (int c = 0; c < CT; c++) acc[s][c] = sb[c];

    constexpr int NIW = (SPT - 1) * S + K;
    const int iwb = ow0 * S - P;

    for (int ci = 0; ci < CIN; ci++) {
        #pragma unroll
        for (int kh = 0; kh < K; kh++) {
            int ih = oh * S - P + kh;
            bool rv = ((unsigned)ih < (unsigned)HIN);
            const float* rp = ib + ((size_t)ci * HIN + ih) * WIN;
            float inv[NIW];
            #pragma unroll
            for (int j = 0; j < NIW; j++) {
                int iw = iwb + j;
                inv[j] = (rv && iw >= 0 && iw < WIN) ? rp[iw] : 0.f;
            }
            #pragma unroll
            for (int kw = 0; kw < K; kw++) {
                #pragma unroll
                for (int c4 = 0; c4 < CT / 4; c4++) {
                    float4 wv = *(const float4*)&sw[((ci * K + kh) * K + kw) * CT + c4 * 4];
                    #pragma unroll
                    for (int s = 0; s < SPT; s++) {
                        float v = inv[s * S + kw];
                        acc[s][c4*4+0] = fmaf(v, wv.x, acc[s][c4*4+0]);
                        acc[s][c4*4+1] = fmaf(v, wv.y, acc[s][c4*4+1]);
                        acc[s][c4*4+2] = fmaf(v, wv.z, acc[s][c4*4+2]);
                        acc[s][c4*4+3] = fmaf(v, wv.w, acc[s][c4*4+3]);
                    }
                }
            }
        }
    }

    #pragma unroll
    for (int s = 0; s < SPT; s++) {
        int ow = ow0 + s;
        if (ow >= WOUT) continue;
        #pragma unroll
        for (int c = 0; c < CT; c++) {
            float a = acc[s][c];
            if (ACT == 1) a = a >= 0.f ? a : LRELU_SLOPE * a;
            out[(((size_t)nb * COUT + cob + c) * HOUT + oh) * WOUT + ow] = a;
        }
    }
}

// ============ transposed conv k=4 s=2 (gather), 2D register tile ============
template<int CIN, int COUT, int CT, int SPT, int ACT>
__global__ void __launch_bounds__(128)
tconv_t2(const float* __restrict__ in, const float* __restrict__ w,
         const float* __restrict__ bias, float* __restrict__ out,
         int HIN, int WIN, int HOUT, int WOUT, int GW)
{
    const int cob = blockIdx.y * CT;
    const int nb  = blockIdx.z;

    __shared__ __align__(16) float sw[CIN * 16 * CT];
    __shared__ float sb[CT];
    for (int i = threadIdx.x; i < CIN * 16 * CT; i += blockDim.x) {
        int ci = i / (16 * CT);
        int r  = i - ci * 16 * CT;
        int tap = r / CT, co = r - tap * CT;
        sw[i] = w[((size_t)ci * COUT + cob + co) * 16 + tap];
    }
    if (threadIdx.x < CT) sb[threadIdx.x] = bias[cob + threadIdx.x];
    __syncthreads();

    int g = blockIdx.x * blockDim.x + threadIdx.x;
    if (g >= HOUT * GW) return;
    int oh  = g / GW;
    int ow0 = (g - oh * GW) * SPT;
    const int hpar = oh & 1;

    const float* ib = in + (size_t)nb * CIN * HIN * WIN;

    float acc[SPT][CT];
    #pragma unroll
    for (int s = 0; s < SPT; s++)
        #pragma unroll
        for (int c = 0; c < CT; c++) acc[s][c] = sb[c];

    constexpr int NIW = SPT / 2 + 1;
    const int iwb = (ow0 >> 1) - 1;

    for (int ci = 0; ci < CIN; ci++) {
        #pragma unroll
        for (int dkh = 0; dkh < 2; dkh++) {
            int kh = hpar + 2 * dkh;
            int t  = oh - kh;
            int ih = t >> 1;
            bool rv = (t >= 0) && (ih < HIN);
            const float* rp = ib + ((size_t)ci * HIN + ih) * WIN;
            float inv[NIW];
            #pragma unroll
            for (int j = 0; j < NIW; j++) {
                int iw = iwb + j;
                inv[j] = (rv && iw >= 0 && iw < WIN) ? rp[iw] : 0.f;
            }
            #pragma unroll
            for (int dkw = 0; dkw < 2; dkw++) {
                #pragma unroll
                for (int wpar = 0; wpar < 2; wpar++) {
                    int tap = kh * 4 + wpar + 2 * dkw;
                    if (CT >= 4) {
                        #pragma unroll
                        for (int c4 = 0; c4 < CT / 4; c4++) {
                            float4 wv = *(const float4*)&sw[(ci * 16 + tap) * CT + c4 * 4];
                            #pragma unroll
                            for (int s = wpar; s < SPT; s += 2) {
                                float v = inv[s / 2 + 1 - dkw];
                                acc[s][c4*4+0] = fmaf(v, wv.x, acc[s][c4*4+0]);
                                acc[s][c4*4+1] = fmaf(v, wv.y, acc[s][c4*4+1]);
                                acc[s][c4*4+2] = fmaf(v, wv.z, acc[s][c4*4+2]);
                                acc[s][c4*4+3] = fmaf(v, wv.w, acc[s][c4*4+3]);
                            }
                        }
                    } else {
                        #pragma unroll
                        for (int c = 0; c < CT; c++) {
                            float wa = sw[(ci * 16 + tap) * CT + c];
                            #pragma unroll
                            for (int s = wpar; s < SPT; s += 2)
                                acc[s][c] = fmaf(inv[s / 2 + 1 - dkw], wa, acc[s][c]);
                        }
                    }
                }
            }
        }
    }

    #pragma unroll
    for (int s = 0; s < SPT; s++) {
        int ow = ow0 + s;
        if (ow >= WOUT) continue;
        #pragma unroll
        for (int c = 0; c < CT; c++) {
            float a = acc[s][c];
            if (ACT == 1) a = a >= 0.f ? a : LRELU_SLOPE * a;
            if (ACT == 2) a = tanhf(a);
            out[(((size_t)nb * COUT + cob + c) * HOUT + oh) * WOUT + ow] = a;
        }
    }
}

// ---------------- codebook squared norms ----------------
__global__ void cnorm_k(const float* __restrict__ cb)
{
    int c = blockIdx.x * blockDim.x + threadIdx.x;
    if (c < 512) {
        float s = 0.f;
        #pragma unroll
        for (int d = 0; d < 64; d++) {
            float v = cb[c * 64 + d];
            s = fmaf(v, v, s);
        }
        g_cnorm[c] = s;
    }
}

// --------- VQ: 2 positions/thread, argmax(dot - 0.5*||c||^2) -----------
__global__ void __launch_bounds__(128) vq2_k(const float* __restrict__ e5,
                                             const float* __restrict__ cb,
                                             float* __restrict__ z)
{
    __shared__ __align__(16) float scb[128 * 64];
    __shared__ float scn[128];
    __shared__ float red[128];

    const int gid = blockIdx.x * 128 + threadIdx.x;
    const int n0 = gid, n1 = gid + 28800;
    const int b0 = n0 / 900, sp0 = n0 - b0 * 900;
    const int b1 = n1 / 900, sp1 = n1 - b1 * 900;

    float lat0[64], lat1[64];
    float fn0 = 0.f, fn1 = 0.f;
    #pragma unroll
    for (int d = 0; d < 64; d++) {
        float v0 = e5[((size_t)(b0 * 64 + d)) * 900 + sp0];
        float v1 = e5[((size_t)(b1 * 64 + d)) * 900 + sp1];
        lat0[d] = v0; lat1[d] = v1;
        fn0 = fmaf(v0, v0, fn0);
        fn1 = fmaf(v1, v1, fn1);
    }

    float best0 = -1e30f, best1 = -1e30f;
    int bi0 = 0, bi1 = 0;
    for (int cbase = 0; cbase < 512; cbase += 128) {
        const float4* src = (const float4*)(cb + cbase * 64);
        float4* dst = (float4*)scb;
        for (int i = threadIdx.x; i < 2048; i += 128) dst[i] = src[i];
        if (threadIdx.x < 128) scn[threadIdx.x] = g_cnorm[cbase + threadIdx.x];
        __syncthreads();

        for (int c = 0; c < 128; c++) {
            const float4* cp = (const float4*)&scb[c * 64];
            float a0 = 0.f, a1 = 0.f, b0a = 0.f, b1a = 0.f;
            #pragma unroll
            for (int q = 0; q < 16; q += 2) {
                float4 w0 = cp[q], w1 = cp[q + 1];
                a0 = fmaf(lat0[4*q+0], w0.x, a0); a0 = fmaf(lat0[4*q+1], w0.y, a0);
                a0 = fmaf(lat0[4*q+2], w0.z, a0); a0 = fmaf(lat0[4*q+3], w0.w, a0);
                b0a = fmaf(lat0[4*q+4], w1.x, b0a); b0a = fmaf(lat0[4*q+5], w1.y, b0a);
                b0a = fmaf(lat0[4*q+6], w1.z, b0a); b0a = fmaf(lat0[4*q+7], w1.w, b0a);
                a1 = fmaf(lat1[4*q+0], w0.x, a1); a1 = fmaf(lat1[4*q+1], w0.y, a1);
                a1 = fmaf(lat1[4*q+2], w0.z, a1); a1 = fmaf(lat1[4*q+3], w0.w, a1);
                b1a = fmaf(lat1[4*q+4], w1.x, b1a); b1a = fmaf(lat1[4*q+5], w1.y, b1a);
                b1a = fmaf(lat1[4*q+6], w1.z, b1a); b1a = fmaf(lat1[4*q+7], w1.w, b1a);
            }
            float hn = 0.5f * scn[c];
            float s0 = a0 + b0a - hn;
            float s1 = a1 + b1a - hn;
            if (s0 > best0) { best0 = s0; bi0 = cbase + c; }
            if (s1 > best1) { best1 = s1; bi1 = cbase + c; }
        }
        __syncthreads();
    }

    const float* cq0 = cb + bi0 * 64;
    const float* cq1 = cb + bi1 * 64;
    #pragma unroll
    for (int d = 0; d < 64; d++) {
        z[((size_t)(b0 * 64 + d)) * 900 + sp0] = cq0[d];
        z[((size_t)(b1 * 64 + d)) * 900 + sp1] = cq1[d];
    }

    red[threadIdx.x] = (fn0 - 2.f * best0) + (fn1 - 2.f * best1);
    __syncthreads();
    for (int s = 64; s > 0; s >>= 1) {
        if (threadIdx.x < s) red[threadIdx.x] += red[threadIdx.x + s];
        __syncthreads();
    }
    if (threadIdx.x == 0) g_partial[blockIdx.x] = red[0];
}

// ---------------- deterministic loss finalize ----------------
__global__ void loss_fin(float* __restrict__ out, int out_size)
{
    __shared__ float red[256];
    float v = (threadIdx.x < 225) ? g_partial[threadIdx.x] : 0.f;
    red[threadIdx.x] = v;
    __syncthreads();
    for (int s = 128; s > 0; s >>= 1) {
        if (threadIdx.x < s) red[threadIdx.x] += red[threadIdx.x + s];
        __syncthreads();
    }
    if (threadIdx.x == 0)
        out[out_size - 1] = 1.25f * red[0] / 3686400.0f;
}

// ============== d1 (3x3, CIN=64, COUT=32, 30x30, pad 1) via tf32 MMA ========
// wT prep: [tap 9][ci 64][co 32], tf32-rounded. dw1 is [32,64,3,3].
__global__ void wprep_d1(const float* __restrict__ w, float* __restrict__ wT)
{
    int i = blockIdx.x * 256 + threadIdx.x;
    if (i >= 18432) return;
    int tap = i / 2048;
    int r   = i - tap * 2048;
    int ci  = r >> 5, co = r & 31;
    float v = w[((size_t)co * 64 + ci) * 9 + tap];
    uint32_t tv; asm("cvt.rna.tf32.f32 %0, %1;" : "=r"(tv) : "f"(v));
    wT[i] = __uint_as_float(tv);
}

// Block = one (b, oh). M=32 (co), N=32 (ow; 30 valid), K = 9 taps x 64 ci.
// 4 warps: warp w -> quadrant (mq = w&1 over co, nq = w>>1 over ow), each
// computing two m16n8 tiles. mma.sync.m16n8k8.tf32.
__global__ void __launch_bounds__(128) d1_tf32(const float* __restrict__ in,
                                               const float* __restrict__ wT,
                                               const float* __restrict__ bias,
                                               float* __restrict__ out)
{
    __shared__ float Bs[64 * 36];   // input rows [ci][j], j = ow_index + kw
    __shared__ float As[64 * 33];   // weights [ci][co], padded

    const int oh = blockIdx.x;      // 0..29
    const int b  = blockIdx.y;      // 0..63
    const int tid = threadIdx.x;
    const int lane = tid & 31, warp = tid >> 5;
    const int mq = warp & 1, nq = warp >> 1;
    const int g = lane >> 2, t = lane & 3;

    float c0[4] = {0.f, 0.f, 0.f, 0.f};
    float c1[4] = {0.f, 0.f, 0.f, 0.f};

    const float* ib = in + (size_t)b * 64 * 900;

    for (int kh = 0; kh < 3; kh++) {
        int ih = oh + kh - 1;
        bool rv = ((unsigned)ih < 30u);
        __syncthreads();
        // stage B: Bs[ci][j] = tf32(in[ci, ih, j-1]), zero at borders
        for (int idx = tid; idx < 64 * 34; idx += 128) {
            int ci = idx / 34, j = idx - ci * 34;
            float v = 0.f;
            if (rv && j >= 1 && j <= 30) v = ib[ci * 900 + ih * 30 + (j - 1)];
            uint32_t tv; asm("cvt.rna.tf32.f32 %0, %1;" : "=r"(tv) : "f"(v));
            Bs[ci * 36 + j] = __uint_as_float(tv);
        }
        for (int kw = 0; kw < 3; kw++) {
            __syncthreads();
            const float* wsrc = wT + (kh * 3 + kw) * 2048;
            for (int idx = tid; idx < 2048; idx += 128) {
                int ci = idx >> 5, co = idx & 31;
                As[ci * 33 + co] = wsrc[idx];
            }
            __syncthreads();
            #pragma unroll
            for (int ck = 0; ck < 8; ck++) {
                int k0 = ck * 8 + t;
                uint32_t a0 = __float_as_uint(As[k0 * 33 + mq * 16 + g]);
                uint32_t a1 = __float_as_uint(As[k0 * 33 + mq * 16 + g + 8]);
                uint32_t a2 = __float_as_uint(As[(k0 + 4) * 33 + mq * 16 + g]);
                uint32_t a3 = __float_as_uint(As[(k0 + 4) * 33 + mq * 16 + g + 8]);

                int owc = nq * 16 + g;   // n-tile 0 column
                uint32_t b0 = __float_as_uint(Bs[k0 * 36 + owc + kw]);
                uint32_t b1 = __float_as_uint(Bs[(k0 + 4) * 36 + owc + kw]);
                asm volatile("mma.sync.aligned.m16n8k8.row.col.f32.tf32.tf32.f32 "
                    "{%0,%1,%2,%3}, {%4,%5,%6,%7}, {%8,%9}, {%0,%1,%2,%3};"
                    : "+f"(c0[0]), "+f"(c0[1]), "+f"(c0[2]), "+f"(c0[3])
                    : "r"(a0), "r"(a1), "r"(a2), "r"(a3), "r"(b0), "r"(b1));

                uint32_t b2 = __float_as_uint(Bs[k0 * 36 + owc + 8 + kw]);
                uint32_t b3 = __float_as_uint(Bs[(k0 + 4) * 36 + owc + 8 + kw]);
                asm volatile("mma.sync.aligned.m16n8k8.row.col.f32.tf32.tf32.f32 "
                    "{%0,%1,%2,%3}, {%4,%5,%6,%7}, {%8,%9}, {%0,%1,%2,%3};"
                    : "+f"(c1[0]), "+f"(c1[1]), "+f"(c1[2]), "+f"(c1[3])
                    : "r"(a0), "r"(a1), "r"(a2), "r"(a3), "r"(b2), "r"(b3));
            }
        }
    }

    // epilogue: c[i] -> (row, col): c0:(g,2t) c1:(g,2t+1) c2:(g+8,2t) c3:(g+8,2t+1)
    #pragma unroll
    for (int nt = 0; nt < 2; nt++) {
        const float* cc = nt ? c1 : c0;
        int owb = nq * 16 + nt * 8 + 2 * t;
        #pragma unroll
        for (int half = 0; half < 2; half++) {
            int co = mq * 16 + g + half * 8;
            float bia = bias[co];
            #pragma unroll
            for (int x = 0; x < 2; x++) {
                int ow = owb + x;
                if (ow < 30) {
                    float v = cc[half * 2 + x] + bia;
                    v = v >= 0.f ? v : LRELU_SLOPE * v;
                    out[(((size_t)b * 32 + co) * 30 + oh) * 30 + ow] = v;
                }
            }
        }
    }
}

// ---------------- launch ----------------
extern "C" void kernel_launch(void* const* d_in, const int* in_sizes, int n_in,
                              void* d_out, int out_size)
{
    (void)in_sizes; (void)n_in;
    const float* x   = (const float*)d_in[0];
    const float* ew1 = (const float*)d_in[1];  const float* eb1 = (const float*)d_in[2];
    const float* ew2 = (const float*)d_in[3];  const float* eb2 = (const float*)d_in[4];
    const float* ew3 = (const float*)d_in[5];  const float* eb3 = (const float*)d_in[6];
    const float* ew4 = (const float*)d_in[7];  const float* eb4 = (const float*)d_in[8];
    const float* ew5 = (const float*)d_in[9];  const float* eb5 = (const float*)d_in[10];
    const float* dw1 = (const float*)d_in[11]; const float* db1 = (const float*)d_in[12];
    const float* dw2 = (const float*)d_in[13]; const float* db2 = (const float*)d_in[14];
    const float* dw3 = (const float*)d_in[15]; const float* db3 = (const float*)d_in[16];
    const float* dw4 = (const float*)d_in[17]; const float* db4 = (const float*)d_in[18];
    const float* cbk = (const float*)d_in[19];
    float* out = (float*)d_out;

    float *bufA, *bufB, *wT;
    cudaGetSymbolAddress((void**)&bufA, g_bufA);
    cudaGetSymbolAddress((void**)&bufB, g_bufB);
    cudaGetSymbolAddress((void**)&wT,   g_wT);

    const int B = 64;

    // d1 weight prep (independent; runs early)
    wprep_d1<<<72, 256>>>(dw1, wT);

    // ---- encoder ----
    conv_t2<1, 8, 8, 4, 2, 0, 4, 1><<<dim3(32, 1, B), 128>>>(x, ew1, eb1, bufA, 256, 256, 127, 127, 32);
    conv_t2<8, 16, 16, 4, 2, 0, 2, 1><<<dim3(16, 1, B), 128>>>(bufA, ew2, eb2, bufB, 127, 127, 62, 62, 31);
    conv_t2<16, 32, 8, 4, 2, 0, 5, 1><<<dim3(2, 4, B), 96>>>(bufB, ew3, eb3, bufA, 62, 62, 30, 30, 6);
    conv_t2<32, 32, 8, 3, 1, 1, 5, 1><<<dim3(2, 4, B), 96>>>(bufA, ew4, eb4, bufB, 30, 30, 30, 30, 6);
    conv_t2<32, 64, 16, 1, 1, 0, 4, 1><<<dim3(2, 4, B), 128>>>(bufB, ew5, eb5, bufA, 30, 30, 30, 30, 8);

    // ---- VQ ----
    cnorm_k<<<2, 256>>>(cbk);
    vq2_k<<<225, 128>>>(bufA, cbk, bufB);

    // ---- decoder ----
    // d1 via tf32 tensor cores: z (bufB) -> bufA
    d1_tf32<<<dim3(30, 64), 128>>>(bufB, wT, db1, bufA);
    // t2: 32->16, 30 -> 63
    tconv_t2<32, 16, 8, 4, 1><<<dim3(8, 2, B), 128>>>(bufA, dw2, db2, bufB, 30, 30, 63, 63, 16);
    // t3: 16->8, 63 -> 129
    tconv_t2<16, 8, 8, 4, 1><<<dim3(34, 1, B), 128>>>(bufB, dw3, db3, bufA, 63, 63, 129, 129, 33);
    // t4: 8->1, 129 -> 260, tanh
    tconv_t2<8, 1, 1, 8, 2><<<dim3(68, 1, B), 128>>>(bufA, dw4, db4, out, 129, 129, 260, 260, 33);

    // ---- loss scalar ----
    loss_fin<<<1, 256>>>(out, out_size);
}

// round 7
// speedup vs baseline: 1.1645x; 1.0272x over previous
#include <cuda_runtime.h>
#include <math.h>
#include <stdint.h>

// ---------------- static scratch (no allocations allowed) ----------------
__device__ float g_bufA[8520192];
__device__ float g_bufB[8520192];
__device__ float g_wT[18432];     // d1 weights tf32 [tap][ci][co]
__device__ float g_wT2[8192];     // t2 weights tf32 [cls][dk][ci][co]
__device__ float g_wT3[2048];     // t3 weights tf32 [cls][dk][ci][co]
__device__ float g_cnorm[512];
__device__ float g_partial[256];

#define LRELU_SLOPE 0.01f

__device__ __forceinline__ float tf32r(float v) {
    uint32_t t; asm("cvt.rna.tf32.f32 %0, %1;" : "=r"(t) : "f"(v));
    return __uint_as_float(t);
}

#define MMA_TF32(C, A0, A1, A2, A3, B0, B1) \
    asm volatile("mma.sync.aligned.m16n8k8.row.col.f32.tf32.tf32.f32 " \
        "{%0,%1,%2,%3}, {%4,%5,%6,%7}, {%8,%9}, {%0,%1,%2,%3};" \
        : "+f"((C)[0]), "+f"((C)[1]), "+f"((C)[2]), "+f"((C)[3]) \
        : "r"(A0), "r"(A1), "r"(A2), "r"(A3), "r"(B0), "r"(B1))

// ================= conv2d scalar (encoder) =================
template<int CIN, int COUT, int CT, int K, int S, int P, int SPT, int ACT>
__global__ void __launch_bounds__(128)
conv_t2(const float* __restrict__ in, const float* __restrict__ w,
        const float* __restrict__ bias, float* __restrict__ out,
        int HIN, int WIN, int HOUT, int WOUT, int GW)
{
    const int cob = blockIdx.y * CT;
    const int nb  = blockIdx.z;

    __shared__ __align__(16) float sw[CIN * K * K * CT];
    __shared__ float sb[CT];
    for (int i = threadIdx.x; i < CIN * K * K * CT; i += blockDim.x) {
        int tap = i / CT, co = i - tap * CT;
        sw[i] = w[(size_t)(cob + co) * CIN * K * K + tap];
    }
    if (threadIdx.x < CT) sb[threadIdx.x] = bias[cob + threadIdx.x];
    __syncthreads();

    int g = blockIdx.x * blockDim.x + threadIdx.x;
    if (g >= HOUT * GW) return;
    int oh  = g / GW;
    int ow0 = (g - oh * GW) * SPT;

    const float* ib = in + (size_t)nb * CIN * HIN * WIN;
    float acc[SPT][CT];
    #pragma unroll
    for (int s = 0; s < SPT; s++)
        #pragma unroll
        for (int c = 0; c < CT; c++) acc[s][c] = sb[c];

    constexpr int NIW = (SPT - 1) * S + K;
    const int iwb = ow0 * S - P;

    for (int ci = 0; ci < CIN; ci++) {
        #pragma unroll
        for (int kh = 0; kh < K; kh++) {
            int ih = oh * S - P + kh;
            bool rv = ((unsigned)ih < (unsigned)HIN);
            const float* rp = ib + ((size_t)ci * HIN + ih) * WIN;
            float inv[NIW];
            #pragma unroll
            for (int j = 0; j < NIW; j++) {
                int iw = iwb + j;
                inv[j] = (rv && iw >= 0 && iw < WIN) ? rp[iw] : 0.f;
            }
            #pragma unroll
            for (int kw = 0; kw < K; kw++) {
                #pragma unroll
                for (int c4 = 0; c4 < CT / 4; c4++) {
                    float4 wv = *(const float4*)&sw[((ci * K + kh) * K + kw) * CT + c4 * 4];
                    #pragma unroll
                    for (int s = 0; s < SPT; s++) {
                        float v = inv[s * S + kw];
                        acc[s][c4*4+0] = fmaf(v, wv.x, acc[s][c4*4+0]);
                        acc[s][c4*4+1] = fmaf(v, wv.y, acc[s][c4*4+1]);
                        acc[s][c4*4+2] = fmaf(v, wv.z, acc[s][c4*4+2]);
                        acc[s][c4*4+3] = fmaf(v, wv.w, acc[s][c4*4+3]);
                    }
                }
            }
        }
    }
    #pragma unroll
    for (int s = 0; s < SPT; s++) {
        int ow = ow0 + s;
        if (ow >= WOUT) continue;
        #pragma unroll
        for (int c = 0; c < CT; c++) {
            float a = acc[s][c];
            if (ACT == 1) a = a >= 0.f ? a : LRELU_SLOPE * a;
            out[(((size_t)nb * COUT + cob + c) * HOUT + oh) * WOUT + ow] = a;
        }
    }
}

// ============ scalar transposed conv (kept for t4) ============
template<int CIN, int COUT, int CT, int SPT, int ACT>
__global__ void __launch_bounds__(128)
tconv_t2(const float* __restrict__ in, const float* __restrict__ w,
         const float* __restrict__ bias, float* __restrict__ out,
         int HIN, int WIN, int HOUT, int WOUT, int GW)
{
    const int cob = blockIdx.y * CT;
    const int nb  = blockIdx.z;

    __shared__ __align__(16) float sw[CIN * 16 * CT];
    __shared__ float sb[CT];
    for (int i = threadIdx.x; i < CIN * 16 * CT; i += blockDim.x) {
        int ci = i / (16 * CT);
        int r  = i - ci * 16 * CT;
        int tap = r / CT, co = r - tap * CT;
        sw[i] = w[((size_t)ci * COUT + cob + co) * 16 + tap];
    }
    if (threadIdx.x < CT) sb[threadIdx.x] = bias[cob + threadIdx.x];
    __syncthreads();

    int g = blockIdx.x * blockDim.x + threadIdx.x;
    if (g >= HOUT * GW) return;
    int oh  = g / GW;
    int ow0 = (g - oh * GW) * SPT;
    const int hpar = oh & 1;

    const float* ib = in + (size_t)nb * CIN * HIN * WIN;
    float acc[SPT][CT];
    #pragma unroll
    for (int s = 0; s < SPT; s++)
        #pragma unroll
        for (int c = 0; c < CT; c++) acc[s][c] = sb[c];

    constexpr int NIW = SPT / 2 + 1;
    const int iwb = (ow0 >> 1) - 1;

    for (int ci = 0; ci < CIN; ci++) {
        #pragma unroll
        for (int dkh = 0; dkh < 2; dkh++) {
            int kh = hpar + 2 * dkh;
            int t  = oh - kh;
            int ih = t >> 1;
            bool rv = (t >= 0) && (ih < HIN);
            const float* rp = ib + ((size_t)ci * HIN + ih) * WIN;
            float inv[NIW];
            #pragma unroll
            for (int j = 0; j < NIW; j++) {
                int iw = iwb + j;
                inv[j] = (rv && iw >= 0 && iw < WIN) ? rp[iw] : 0.f;
            }
            #pragma unroll
            for (int dkw = 0; dkw < 2; dkw++) {
                #pragma unroll
                for (int wpar = 0; wpar < 2; wpar++) {
                    int tap = kh * 4 + wpar + 2 * dkw;
                    #pragma unroll
                    for (int c = 0; c < CT; c++) {
                        float wa = sw[(ci * 16 + tap) * CT + c];
                        #pragma unroll
                        for (int s = wpar; s < SPT; s += 2)
                            acc[s][c] = fmaf(inv[s / 2 + 1 - dkw], wa, acc[s][c]);
                    }
                }
            }
        }
    }
    #pragma unroll
    for (int s = 0; s < SPT; s++) {
        int ow = ow0 + s;
        if (ow >= WOUT) continue;
        #pragma unroll
        for (int c = 0; c < CT; c++) {
            float a = acc[s][c];
            if (ACT == 1) a = a >= 0.f ? a : LRELU_SLOPE * a;
            if (ACT == 2) a = tanhf(a);
            out[(((size_t)nb * COUT + cob + c) * HOUT + oh) * WOUT + ow] = a;
        }
    }
}

// ---------------- codebook squared norms ----------------
__global__ void cnorm_k(const float* __restrict__ cb)
{
    int c = blockIdx.x * blockDim.x + threadIdx.x;
    if (c < 512) {
        float s = 0.f;
        #pragma unroll
        for (int d = 0; d < 64; d++) {
            float v = cb[c * 64 + d];
            s = fmaf(v, v, s);
        }
        g_cnorm[c] = s;
    }
}

// --------- VQ: 2 positions/thread ----------
__global__ void __launch_bounds__(128) vq2_k(const float* __restrict__ e5,
                                             const float* __restrict__ cb,
                                             float* __restrict__ z)
{
    __shared__ __align__(16) float scb[128 * 64];
    __shared__ float scn[128];
    __shared__ float red[128];

    const int gid = blockIdx.x * 128 + threadIdx.x;
    const int n0 = gid, n1 = gid + 28800;
    const int b0 = n0 / 900, sp0 = n0 - b0 * 900;
    const int b1 = n1 / 900, sp1 = n1 - b1 * 900;

    float lat0[64], lat1[64];
    float fn0 = 0.f, fn1 = 0.f;
    #pragma unroll
    for (int d = 0; d < 64; d++) {
        float v0 = e5[((size_t)(b0 * 64 + d)) * 900 + sp0];
        float v1 = e5[((size_t)(b1 * 64 + d)) * 900 + sp1];
        lat0[d] = v0; lat1[d] = v1;
        fn0 = fmaf(v0, v0, fn0);
        fn1 = fmaf(v1, v1, fn1);
    }

    float best0 = -1e30f, best1 = -1e30f;
    int bi0 = 0, bi1 = 0;
    for (int cbase = 0; cbase < 512; cbase += 128) {
        const float4* src = (const float4*)(cb + cbase * 64);
        float4* dst = (float4*)scb;
        for (int i = threadIdx.x; i < 2048; i += 128) dst[i] = src[i];
        scn[threadIdx.x] = g_cnorm[cbase + threadIdx.x];
        __syncthreads();

        for (int c = 0; c < 128; c++) {
            const float4* cp = (const float4*)&scb[c * 64];
            float a0 = 0.f, a1 = 0.f, b0a = 0.f, b1a = 0.f;
            #pragma unroll
            for (int q = 0; q < 16; q += 2) {
                float4 w0 = cp[q], w1 = cp[q + 1];
                a0 = fmaf(lat0[4*q+0], w0.x, a0); a0 = fmaf(lat0[4*q+1], w0.y, a0);
                a0 = fmaf(lat0[4*q+2], w0.z, a0); a0 = fmaf(lat0[4*q+3], w0.w, a0);
                b0a = fmaf(lat0[4*q+4], w1.x, b0a); b0a = fmaf(lat0[4*q+5], w1.y, b0a);
                b0a = fmaf(lat0[4*q+6], w1.z, b0a); b0a = fmaf(lat0[4*q+7], w1.w, b0a);
                a1 = fmaf(lat1[4*q+0], w0.x, a1); a1 = fmaf(lat1[4*q+1], w0.y, a1);
                a1 = fmaf(lat1[4*q+2], w0.z, a1); a1 = fmaf(lat1[4*q+3], w0.w, a1);
                b1a = fmaf(lat1[4*q+4], w1.x, b1a); b1a = fmaf(lat1[4*q+5], w1.y, b1a);
                b1a = fmaf(lat1[4*q+6], w1.z, b1a); b1a = fmaf(lat1[4*q+7], w1.w, b1a);
            }
            float hn = 0.5f * scn[c];
            float s0 = a0 + b0a - hn;
            float s1 = a1 + b1a - hn;
            if (s0 > best0) { best0 = s0; bi0 = cbase + c; }
            if (s1 > best1) { best1 = s1; bi1 = cbase + c; }
        }
        __syncthreads();
    }

    const float* cq0 = cb + bi0 * 64;
    const float* cq1 = cb + bi1 * 64;
    #pragma unroll
    for (int d = 0; d < 64; d++) {
        z[((size_t)(b0 * 64 + d)) * 900 + sp0] = cq0[d];
        z[((size_t)(b1 * 64 + d)) * 900 + sp1] = cq1[d];
    }

    red[threadIdx.x] = (fn0 - 2.f * best0) + (fn1 - 2.f * best1);
    __syncthreads();
    for (int s = 64; s > 0; s >>= 1) {
        if (threadIdx.x < s) red[threadIdx.x] += red[threadIdx.x + s];
        __syncthreads();
    }
    if (threadIdx.x == 0) g_partial[blockIdx.x] = red[0];
}

// ---------------- deterministic loss finalize ----------------
__global__ void loss_fin(float* __restrict__ out, int out_size)
{
    __shared__ float red[256];
    float v = (threadIdx.x < 225) ? g_partial[threadIdx.x] : 0.f;
    red[threadIdx.x] = v;
    __syncthreads();
    for (int s = 128; s > 0; s >>= 1) {
        if (threadIdx.x < s) red[threadIdx.x] += red[threadIdx.x + s];
        __syncthreads();
    }
    if (threadIdx.x == 0)
        out[out_size - 1] = 1.25f * red[0] / 3686400.0f;
}

// ---------------- weight preps ----------------
__global__ void wprep_d1(const float* __restrict__ w, float* __restrict__ wT)
{
    int i = blockIdx.x * 256 + threadIdx.x;
    if (i >= 18432) return;
    int tap = i / 2048;
    int r   = i - tap * 2048;
    int ci  = r >> 5, co = r & 31;
    wT[i] = tf32r(w[((size_t)co * 64 + ci) * 9 + tap]);
}

// tconv class weights: dst[((cls*4+dk)*CIN+ci)*COUT+co] = w[ci][co][hp+2dkh][wp+2dkw]
template<int CIN, int COUT>
__global__ void wprep_tc(const float* __restrict__ w, float* __restrict__ dst)
{
    int i = blockIdx.x * 256 + threadIdx.x;
    if (i >= 16 * CIN * COUT) return;
    int co = i % COUT;
    int ci = (i / COUT) % CIN;
    int dk = (i / (COUT * CIN)) % 4;
    int cls = i / (COUT * CIN * 4);
    int hp = cls >> 1, wp = cls & 1;
    int dkh = dk >> 1, dkw = dk & 1;
    dst[i] = tf32r(w[((size_t)ci * COUT + co) * 16 + (hp + 2 * dkh) * 4 + (wp + 2 * dkw)]);
}

// ============== d1 v2: 3x3 conv 64->32 pad1 via tf32 MMA ==============
// block = (oh pair, batch), 256 thr = 8 warps (2 m-quads x 4 n-quads).
__global__ void __launch_bounds__(256)
d1_mma(const float* __restrict__ in, const float* __restrict__ wT,
       const float* __restrict__ bias, float* __restrict__ out)
{
    __shared__ float As[64 * 33];    // per-tap weights [ci][co]
    __shared__ float Bs[64 * 136];   // input [ci][r4:4][j:34] tf32

    const int oh0 = blockIdx.x * 2;
    const int b   = blockIdx.y;
    const int tid = threadIdx.x;

    const float* ib = in + (size_t)b * 64 * 900;
    for (int i = tid; i < 8704; i += 256) {
        int ci = i / 136; int rem = i - ci * 136;
        int r4 = rem / 34; int j = rem - r4 * 34;
        int ih = oh0 - 1 + r4; int iw = j - 1;
        float v = 0.f;
        if ((unsigned)ih < 30u && (unsigned)iw < 30u) v = ib[ci * 900 + ih * 30 + iw];
        Bs[i] = tf32r(v);
    }

    const int lane = tid & 31, warp = tid >> 5;
    const int mq = warp & 1, nw = warp >> 1;
    const int g = lane >> 2, t = lane & 3;
    const int rW = nw >> 1;
    const int owb = (nw & 1) * 16;

    float c0[4] = {0.f, 0.f, 0.f, 0.f};
    float c1[4] = {0.f, 0.f, 0.f, 0.f};

    for (int tap = 0; tap < 9; tap++) {
        __syncthreads();
        const float* wsrc = wT + tap * 2048;
        for (int i = tid; i < 2048; i += 256)
            As[(i >> 5) * 33 + (i & 31)] = wsrc[i];
        __syncthreads();

        int kh = tap / 3, kw = tap - kh * 3;
        int boff = (rW + kh) * 34 + owb + g + kw;

        #pragma unroll
        for (int ck = 0; ck < 8; ck++) {
            int k0 = ck * 8 + t;
            const float* wr = As + k0 * 33 + mq * 16 + g;
            uint32_t a0 = __float_as_uint(wr[0]);
            uint32_t a1 = __float_as_uint(wr[8]);
            uint32_t a2 = __float_as_uint(wr[4 * 33]);
            uint32_t a3 = __float_as_uint(wr[4 * 33 + 8]);
            uint32_t b0 = __float_as_uint(Bs[k0 * 136 + boff]);
            uint32_t b1 = __float_as_uint(Bs[(k0 + 4) * 136 + boff]);
            MMA_TF32(c0, a0, a1, a2, a3, b0, b1);
            uint32_t b2 = __float_as_uint(Bs[k0 * 136 + boff + 8]);
            uint32_t b3 = __float_as_uint(Bs[(k0 + 4) * 136 + boff + 8]);
            MMA_TF32(c1, a0, a1, a2, a3, b2, b3);
        }
    }

    const int oh = oh0 + rW;
    #pragma unroll
    for (int nt = 0; nt < 2; nt++) {
        const float* cc = nt ? c1 : c0;
        #pragma unroll
        for (int half = 0; half < 2; half++) {
            int co = mq * 16 + g + half * 8;
            float bia = bias[co];
            #pragma unroll
            for (int x = 0; x < 2; x++) {
                int ow = owb + nt * 8 + 2 * t + x;
                if (ow < 30) {
                    float v = cc[half * 2 + x] + bia;
                    v = v >= 0.f ? v : LRELU_SLOPE * v;
                    out[(((size_t)b * 32 + co) * 30 + oh) * 30 + ow] = v;
                }
            }
        }
    }
}

// ====== tconv k4 s2 via parity classes, tf32 MMA; A=positions, B=weights =====
// class (hp,wp): out[2ohh+hp][2oww+wp] = sum_{dk,ci} in[ci][ohh-dkh][oww-dkw]*Wc
template<int CIN, int COUT, int RSTRIP, int JW, int NMT, int NT>
__global__ void __launch_bounds__(256)
tconv_mma(const float* __restrict__ in, const float* __restrict__ wc,
          const float* __restrict__ bias, float* __restrict__ out,
          int HIN, int WIN, int HOUT, int WOUT)
{
    constexpr int KK = 4 * CIN;
    constexpr int CP = COUT + 1;
    constexpr int ISTR = (RSTRIP + 1) * JW;
    constexpr int KSPD = CIN / 8;

    __shared__ float Ws[KK * CP];
    __shared__ float Is[CIN * ISTR];

    const int b = blockIdx.z;
    const int cls = blockIdx.y;
    const int hp = cls >> 1, wp = cls & 1;
    const int NOHH = (HOUT - hp + 1) >> 1;
    const int NOWW = (WOUT - wp + 1) >> 1;
    const int ohh0 = blockIdx.x * RSTRIP;
    const int tid = threadIdx.x;

    const float* wsrc = wc + (size_t)cls * KK * COUT;
    for (int i = tid; i < KK * COUT; i += 256) {
        int k = i / COUT, co = i - k * COUT;
        Ws[k * CP + co] = wsrc[i];
    }
    const float* ibp = in + (size_t)b * CIN * HIN * WIN;
    for (int i = tid; i < CIN * ISTR; i += 256) {
        int ci = i / ISTR; int rem = i - ci * ISTR;
        int rr = rem / JW; int jj = rem - rr * JW;
        int ih = ohh0 - 1 + rr; int iw = jj - 1;
        float v = 0.f;
        if ((unsigned)ih < (unsigned)HIN && (unsigned)iw < (unsigned)WIN)
            v = ibp[ci * HIN * WIN + ih * WIN + iw];
        Is[i] = tf32r(v);
    }
    __syncthreads();

    const int lane = tid & 31, warp = tid >> 5;
    const int g = lane >> 2, t = lane & 3;
    const int MPOS = RSTRIP * NOWW;

    int rA[NMT], oA[NMT], rB[NMT], oB[NMT];
    bool vA[NMT], vB[NMT];
    #pragma unroll
    for (int i = 0; i < NMT; i++) {
        int mt = warp + i * 8;
        int m0 = mt * 16 + g, m1 = m0 + 8;
        int r0 = m0 / NOWW, o0 = m0 - r0 * NOWW;
        int r1 = m1 / NOWW, o1 = m1 - r1 * NOWW;
        vA[i] = (m0 < MPOS) && (ohh0 + r0 < NOHH);
        vB[i] = (m1 < MPOS) && (ohh0 + r1 < NOHH);
        if (m0 >= MPOS) { r0 = 0; o0 = 0; }
        if (m1 >= MPOS) { r1 = 0; o1 = 0; }
        rA[i] = r0; oA[i] = o0; rB[i] = r1; oB[i] = o1;
    }

    float acc[NMT][NT][4];
    #pragma unroll
    for (int i = 0; i < NMT; i++)
        #pragma unroll
        for (int nt = 0; nt < NT; nt++)
            #pragma unroll
            for (int x = 0; x < 4; x++) acc[i][nt][x] = 0.f;

    #pragma unroll
    for (int ck = 0; ck < KK / 8; ck++) {
        int dk = ck / KSPD;
        int dkh = dk >> 1, dkw = dk & 1;
        int k0 = ck * 8 + t;
        int ci0 = k0 - dk * CIN;
        uint32_t bw0[NT], bw1[NT];
        #pragma unroll
        for (int nt = 0; nt < NT; nt++) {
            bw0[nt] = __float_as_uint(Ws[k0 * CP + nt * 8 + g]);
            bw1[nt] = __float_as_uint(Ws[(k0 + 4) * CP + nt * 8 + g]);
        }
        int roff = (1 - dkh) * JW + (1 - dkw);
        #pragma unroll
        for (int i = 0; i < NMT; i++) {
            const float* p0 = Is + ci0 * ISTR + rA[i] * JW + oA[i] + roff;
            const float* p1 = Is + ci0 * ISTR + rB[i] * JW + oB[i] + roff;
            uint32_t a0 = __float_as_uint(p0[0]);
            uint32_t a1 = __float_as_uint(p1[0]);
            uint32_t a2 = __float_as_uint(p0[4 * ISTR]);
            uint32_t a3 = __float_as_uint(p1[4 * ISTR]);
            #pragma unroll
            for (int nt = 0; nt < NT; nt++)
                MMA_TF32(acc[i][nt], a0, a1, a2, a3, bw0[nt], bw1[nt]);
        }
    }

    #pragma unroll
    for (int i = 0; i < NMT; i++) {
        #pragma unroll
        for (int nt = 0; nt < NT; nt++) {
            #pragma unroll
            for (int x = 0; x < 2; x++) {
                int co = nt * 8 + 2 * t + x;
                float bia = bias[co];
                if (vA[i]) {
                    int oh = 2 * (ohh0 + rA[i]) + hp;
                    int ow = 2 * oA[i] + wp;
                    float v = acc[i][nt][x] + bia;
                    v = v >= 0.f ? v : LRELU_SLOPE * v;
                    out[(((size_t)b * COUT + co) * HOUT + oh) * WOUT + ow] = v;
                }
                if (vB[i]) {
                    int oh = 2 * (ohh0 + rB[i]) + hp;
                    int ow = 2 * oB[i] + wp;
                    float v = acc[i][nt][2 + x] + bia;
                    v = v >= 0.f ? v : LRELU_SLOPE * v;
                    out[(((size_t)b * COUT + co) * HOUT + oh) * WOUT + ow] = v;
                }
            }
        }
    }
}

// ---------------- launch ----------------
extern "C" void kernel_launch(void* const* d_in, const int* in_sizes, int n_in,
                              void* d_out, int out_size)
{
    (void)in_sizes; (void)n_in;
    const float* x   = (const float*)d_in[0];
    const float* ew1 = (const float*)d_in[1];  const float* eb1 = (const float*)d_in[2];
    const float* ew2 = (const float*)d_in[3];  const float* eb2 = (const float*)d_in[4];
    const float* ew3 = (const float*)d_in[5];  const float* eb3 = (const float*)d_in[6];
    const float* ew4 = (const float*)d_in[7];  const float* eb4 = (const float*)d_in[8];
    const float* ew5 = (const float*)d_in[9];  const float* eb5 = (const float*)d_in[10];
    const float* dw1 = (const float*)d_in[11]; const float* db1 = (const float*)d_in[12];
    const float* dw2 = (const float*)d_in[13]; const float* db2 = (const float*)d_in[14];
    const float* dw3 = (const float*)d_in[15]; const float* db3 = (const float*)d_in[16];
    const float* dw4 = (const float*)d_in[17]; const float* db4 = (const float*)d_in[18];
    const float* cbk = (const float*)d_in[19];
    float* out = (float*)d_out;

    float *bufA, *bufB, *wT, *wT2, *wT3;
    cudaGetSymbolAddress((void**)&bufA, g_bufA);
    cudaGetSymbolAddress((void**)&bufB, g_bufB);
    cudaGetSymbolAddress((void**)&wT,   g_wT);
    cudaGetSymbolAddress((void**)&wT2,  g_wT2);
    cudaGetSymbolAddress((void**)&wT3,  g_wT3);

    const int B = 64;

    // weight preps (independent)
    wprep_d1<<<72, 256>>>(dw1, wT);
    wprep_tc<32, 16><<<32, 256>>>(dw2, wT2);
    wprep_tc<16, 8><<<8, 256>>>(dw3, wT3);

    // ---- encoder (fp32 scalar; keeps VQ argmin exact) ----
    conv_t2<1, 8, 8, 4, 2, 0, 4, 1><<<dim3(32, 1, B), 128>>>(x, ew1, eb1, bufA, 256, 256, 127, 127, 32);
    conv_t2<8, 16, 16, 4, 2, 0, 2, 1><<<dim3(16, 1, B), 128>>>(bufA, ew2, eb2, bufB, 127, 127, 62, 62, 31);
    conv_t2<16, 32, 8, 4, 2, 0, 5, 1><<<dim3(2, 4, B), 96>>>(bufB, ew3, eb3, bufA, 62, 62, 30, 30, 6);
    conv_t2<32, 32, 8, 3, 1, 1, 5, 1><<<dim3(2, 4, B), 96>>>(bufA, ew4, eb4, bufB, 30, 30, 30, 30, 6);
    conv_t2<32, 64, 16, 1, 1, 0, 4, 1><<<dim3(2, 4, B), 128>>>(bufB, ew5, eb5, bufA, 30, 30, 30, 30, 8);

    // ---- VQ (fp32) ----
    cnorm_k<<<2, 256>>>(cbk);
    vq2_k<<<225, 128>>>(bufA, cbk, bufB);

    // ---- decoder (tf32 MMA) ----
    d1_mma<<<dim3(15, 64), 256>>>(bufB, wT, db1, bufA);
    // t2: 32->16, 30 -> 63 : 4 classes, strips of 8 ohh rows
    tconv_mma<32, 16, 8, 33, 2, 2><<<dim3(4, 4, B), 256>>>(bufA, wT2, db2, bufB, 30, 30, 63, 63);
    // t3: 16->8, 63 -> 129 : strips of 8 (NOHH up to 65 -> 9 strips)
    tconv_mma<16, 8, 8, 66, 5, 1><<<dim3(9, 4, B), 256>>>(bufB, wT3, db3, bufA, 63, 63, 129, 129);
    // t4: 8->1, 129 -> 260, tanh (scalar)
    tconv_t2<8, 1, 1, 8, 2><<<dim3(68, 1, B), 128>>>(bufA, dw4, db4, out, 129, 129, 260, 260, 33);

    // ---- loss scalar ----
    loss_fin<<<1, 256>>>(out, out_size);
}

// round 8
// speedup vs baseline: 1.4112x; 1.2118x over previous
#include <cuda_runtime.h>
#include <math.h>
#include <stdint.h>

// ---------------- static scratch (no allocations allowed) ----------------
__device__ float g_bufA[8520192];
__device__ float g_bufB[8520192];
__device__ float g_wT[18432];     // d1 weights tf32 [tap][ci][co]
__device__ float g_wT2[8192];     // t2 weights tf32 [cls][dk][ci][co]
__device__ float g_wT3[2048];     // t3 weights tf32 [cls][dk][ci][co]
__device__ float g_cnorm[512];
__device__ float g_partial[512];

#define LRELU_SLOPE 0.01f

__device__ __forceinline__ float tf32r(float v) {
    uint32_t t; asm("cvt.rna.tf32.f32 %0, %1;" : "=r"(t) : "f"(v));
    return __uint_as_float(t);
}

#define MMA_TF32(C, A0, A1, A2, A3, B0, B1) \
    asm volatile("mma.sync.aligned.m16n8k8.row.col.f32.tf32.tf32.f32 " \
        "{%0,%1,%2,%3}, {%4,%5,%6,%7}, {%8,%9}, {%0,%1,%2,%3};" \
        : "+f"((C)[0]), "+f"((C)[1]), "+f"((C)[2]), "+f"((C)[3]) \
        : "r"(A0), "r"(A1), "r"(A2), "r"(A3), "r"(B0), "r"(B1))

// ================= conv2d scalar (encoder) =================
template<int CIN, int COUT, int CT, int K, int S, int P, int SPT, int ACT>
__global__ void __launch_bounds__(128)
conv_t2(const float* __restrict__ in, const float* __restrict__ w,
        const float* __restrict__ bias, float* __restrict__ out,
        int HIN, int WIN, int HOUT, int WOUT, int GW)
{
    const int cob = blockIdx.y * CT;
    const int nb  = blockIdx.z;

    __shared__ __align__(16) float sw[CIN * K * K * CT];
    __shared__ float sb[CT];
    for (int i = threadIdx.x; i < CIN * K * K * CT; i += blockDim.x) {
        int tap = i / CT, co = i - tap * CT;
        sw[i] = w[(size_t)(cob + co) * CIN * K * K + tap];
    }
    if (threadIdx.x < CT) sb[threadIdx.x] = bias[cob + threadIdx.x];
    __syncthreads();

    int g = blockIdx.x * blockDim.x + threadIdx.x;
    if (g >= HOUT * GW) return;
    int oh  = g / GW;
    int ow0 = (g - oh * GW) * SPT;

    const float* ib = in + (size_t)nb * CIN * HIN * WIN;
    float acc[SPT][CT];
    #pragma unroll
    for (int s = 0; s < SPT; s++)
        #pragma unroll
        for (int c = 0; c < CT; c++) acc[s][c] = sb[c];

    constexpr int NIW = (SPT - 1) * S + K;
    const int iwb = ow0 * S - P;

    for (int ci = 0; ci < CIN; ci++) {
        #pragma unroll
        for (int kh = 0; kh < K; kh++) {
            int ih = oh * S - P + kh;
            bool rv = ((unsigned)ih < (unsigned)HIN);
            const float* rp = ib + ((size_t)ci * HIN + ih) * WIN;
            float inv[NIW];
            #pragma unroll
            for (int j = 0; j < NIW; j++) {
                int iw = iwb + j;
                inv[j] = (rv && iw >= 0 && iw < WIN) ? rp[iw] : 0.f;
            }
            #pragma unroll
            for (int kw = 0; kw < K; kw++) {
                #pragma unroll
                for (int c4 = 0; c4 < CT / 4; c4++) {
                    float4 wv = *(const float4*)&sw[((ci * K + kh) * K + kw) * CT + c4 * 4];
                    #pragma unroll
                    for (int s = 0; s < SPT; s++) {
                        float v = inv[s * S + kw];
                        acc[s][c4*4+0] = fmaf(v, wv.x, acc[s][c4*4+0]);
                        acc[s][c4*4+1] = fmaf(v, wv.y, acc[s][c4*4+1]);
                        acc[s][c4*4+2] = fmaf(v, wv.z, acc[s][c4*4+2]);
                        acc[s][c4*4+3] = fmaf(v, wv.w, acc[s][c4*4+3]);
                    }
                }
            }
        }
    }
    #pragma unroll
    for (int s = 0; s < SPT; s++) {
        int ow = ow0 + s;
        if (ow >= WOUT) continue;
        #pragma unroll
        for (int c = 0; c < CT; c++) {
            float a = acc[s][c];
            if (ACT == 1) a = a >= 0.f ? a : LRELU_SLOPE * a;
            out[(((size_t)nb * COUT + cob + c) * HOUT + oh) * WOUT + ow] = a;
        }
    }
}

// ============ scalar transposed conv (kept for t4) ============
template<int CIN, int COUT, int CT, int SPT, int ACT>
__global__ void __launch_bounds__(128)
tconv_t2(const float* __restrict__ in, const float* __restrict__ w,
         const float* __restrict__ bias, float* __restrict__ out,
         int HIN, int WIN, int HOUT, int WOUT, int GW)
{
    const int cob = blockIdx.y * CT;
    const int nb  = blockIdx.z;

    __shared__ __align__(16) float sw[CIN * 16 * CT];
    __shared__ float sb[CT];
    for (int i = threadIdx.x; i < CIN * 16 * CT; i += blockDim.x) {
        int ci = i / (16 * CT);
        int r  = i - ci * 16 * CT;
        int tap = r / CT, co = r - tap * CT;
        sw[i] = w[((size_t)ci * COUT + cob + co) * 16 + tap];
    }
    if (threadIdx.x < CT) sb[threadIdx.x] = bias[cob + threadIdx.x];
    __syncthreads();

    int g = blockIdx.x * blockDim.x + threadIdx.x;
    if (g >= HOUT * GW) return;
    int oh  = g / GW;
    int ow0 = (g - oh * GW) * SPT;
    const int hpar = oh & 1;

    const float* ib = in + (size_t)nb * CIN * HIN * WIN;
    float acc[SPT][CT];
    #pragma unroll
    for (int s = 0; s < SPT; s++)
        #pragma unroll
        for (int c = 0; c < CT; c++) acc[s][c] = sb[c];

    constexpr int NIW = SPT / 2 + 1;
    const int iwb = (ow0 >> 1) - 1;

    for (int ci = 0; ci < CIN; ci++) {
        #pragma unroll
        for (int dkh = 0; dkh < 2; dkh++) {
            int kh = hpar + 2 * dkh;
            int t  = oh - kh;
            int ih = t >> 1;
            bool rv = (t >= 0) && (ih < HIN);
            const float* rp = ib + ((size_t)ci * HIN + ih) * WIN;
            float inv[NIW];
            #pragma unroll
            for (int j = 0; j < NIW; j++) {
                int iw = iwb + j;
                inv[j] = (rv && iw >= 0 && iw < WIN) ? rp[iw] : 0.f;
            }
            #pragma unroll
            for (int dkw = 0; dkw < 2; dkw++) {
                #pragma unroll
                for (int wpar = 0; wpar < 2; wpar++) {
                    int tap = kh * 4 + wpar + 2 * dkw;
                    #pragma unroll
                    for (int c = 0; c < CT; c++) {
                        float wa = sw[(ci * 16 + tap) * CT + c];
                        #pragma unroll
                        for (int s = wpar; s < SPT; s += 2)
                            acc[s][c] = fmaf(inv[s / 2 + 1 - dkw], wa, acc[s][c]);
                    }
                }
            }
        }
    }
    #pragma unroll
    for (int s = 0; s < SPT; s++) {
        int ow = ow0 + s;
        if (ow >= WOUT) continue;
        #pragma unroll
        for (int c = 0; c < CT; c++) {
            float a = acc[s][c];
            if (ACT == 1) a = a >= 0.f ? a : LRELU_SLOPE * a;
            if (ACT == 2) a = tanhf(a);
            out[(((size_t)nb * COUT + cob + c) * HOUT + oh) * WOUT + ow] = a;
        }
    }
}

// ---------------- codebook squared norms (fp32 exact) ----------------
__global__ void cnorm_k(const float* __restrict__ cb)
{
    int c = blockIdx.x * blockDim.x + threadIdx.x;
    if (c < 512) {
        float s = 0.f;
        #pragma unroll
        for (int d = 0; d < 64; d++) {
            float v = cb[c * 64 + d];
            s = fmaf(v, v, s);
        }
        g_cnorm[c] = s;
    }
}

// ======== VQ via split-tf32 MMA + fused argmax (argmin-preserving) ========
// 450 blocks x 256 thr; warp handles 16 positions; all 512 codes looped in
// 64-code smem chunks (hi/lo split, stride 72 => conflict-free B reads).
__global__ void __launch_bounds__(256) vq_mma(const float* __restrict__ e5,
                                              const float* __restrict__ cb,
                                              float* __restrict__ z)
{
    __shared__ float Bh[64 * 72];
    __shared__ float Bl[64 * 72];
    __shared__ float scn[64];
    __shared__ int   sidx[128];
    __shared__ float red[64];

    const int tid = threadIdx.x;
    const int lane = tid & 31, warp = tid >> 5;
    const int g = lane >> 2, t = lane & 3;
    const int p0 = blockIdx.x * 128 + warp * 16 + g;
    const int p1 = p0 + 8;
    const int b0 = p0 / 900, sp0 = p0 - b0 * 900;
    const int b1 = p1 / 900, sp1 = p1 - b1 * 900;

    // A fragments (hi/lo) in registers; fp32 fnorm alongside
    uint32_t ah[8][4], al[8][4];
    float fn0 = 0.f, fn1 = 0.f;
    #pragma unroll
    for (int ck = 0; ck < 8; ck++) {
        int d0 = ck * 8 + t, d1 = d0 + 4;
        float v0 = e5[((size_t)(b0 * 64 + d0)) * 900 + sp0];
        float v1 = e5[((size_t)(b1 * 64 + d0)) * 900 + sp1];
        float v2 = e5[((size_t)(b0 * 64 + d1)) * 900 + sp0];
        float v3 = e5[((size_t)(b1 * 64 + d1)) * 900 + sp1];
        fn0 = fmaf(v0, v0, fmaf(v2, v2, fn0));
        fn1 = fmaf(v1, v1, fmaf(v3, v3, fn1));
        float h;
        h = tf32r(v0); ah[ck][0] = __float_as_uint(h); al[ck][0] = __float_as_uint(tf32r(v0 - h));
        h = tf32r(v1); ah[ck][1] = __float_as_uint(h); al[ck][1] = __float_as_uint(tf32r(v1 - h));
        h = tf32r(v2); ah[ck][2] = __float_as_uint(h); al[ck][2] = __float_as_uint(tf32r(v2 - h));
        h = tf32r(v3); ah[ck][3] = __float_as_uint(h); al[ck][3] = __float_as_uint(tf32r(v3 - h));
    }
    // full fnorm per position across the t-quad (dims partitioned by t mod 4)
    fn0 += __shfl_xor_sync(0xffffffffu, fn0, 1);
    fn0 += __shfl_xor_sync(0xffffffffu, fn0, 2);
    fn1 += __shfl_xor_sync(0xffffffffu, fn1, 1);
    fn1 += __shfl_xor_sync(0xffffffffu, fn1, 2);

    float best0 = -1e30f, best1 = -1e30f;
    int bi0 = 0, bi1 = 0;

    for (int cbase = 0; cbase < 512; cbase += 64) {
        __syncthreads();
        for (int i = tid; i < 4096; i += 256) {
            int c = i >> 6, k = i & 63;
            float v = cb[(size_t)(cbase + c) * 64 + k];
            float h = tf32r(v);
            Bh[k * 72 + c] = h;
            Bl[k * 72 + c] = tf32r(v - h);
        }
        if (tid < 64) scn[tid] = 0.5f * g_cnorm[cbase + tid];
        __syncthreads();

        #pragma unroll
        for (int tile = 0; tile < 8; tile++) {
            float c[4] = {0.f, 0.f, 0.f, 0.f};
            #pragma unroll
            for (int ck = 0; ck < 8; ck++) {
                int k0 = ck * 8 + t;
                uint32_t b0h = __float_as_uint(Bh[k0 * 72 + tile * 8 + g]);
                uint32_t b1h = __float_as_uint(Bh[(k0 + 4) * 72 + tile * 8 + g]);
                uint32_t b0l = __float_as_uint(Bl[k0 * 72 + tile * 8 + g]);
                uint32_t b1l = __float_as_uint(Bl[(k0 + 4) * 72 + tile * 8 + g]);
                MMA_TF32(c, ah[ck][0], ah[ck][1], ah[ck][2], ah[ck][3], b0h, b1h);
                MMA_TF32(c, ah[ck][0], ah[ck][1], ah[ck][2], ah[ck][3], b0l, b1l);
                MMA_TF32(c, al[ck][0], al[ck][1], al[ck][2], al[ck][3], b0h, b1h);
            }
            int col0 = tile * 8 + 2 * t, col1 = col0 + 1;
            float hn0 = scn[col0], hn1 = scn[col1];
            float s;
            s = c[0] - hn0; if (s > best0) { best0 = s; bi0 = cbase + col0; }
            s = c[1] - hn1; if (s > best0) { best0 = s; bi0 = cbase + col1; }
            s = c[2] - hn0; if (s > best1) { best1 = s; bi1 = cbase + col0; }
            s = c[3] - hn1; if (s > best1) { best1 = s; bi1 = cbase + col1; }
        }
    }

    // reduce argmax across the t-quad (prefer higher score, lower idx on tie)
    #pragma unroll
    for (int m = 1; m <= 2; m <<= 1) {
        float so = __shfl_xor_sync(0xffffffffu, best0, m);
        int   io = __shfl_xor_sync(0xffffffffu, bi0, m);
        if (so > best0 || (so == best0 && io < bi0)) { best0 = so; bi0 = io; }
        so = __shfl_xor_sync(0xffffffffu, best1, m);
        io = __shfl_xor_sync(0xffffffffu, bi1, m);
        if (so > best1 || (so == best1 && io < bi1)) { best1 = so; bi1 = io; }
    }
    if (t == 0) {
        sidx[warp * 16 + g] = bi0;
        sidx[warp * 16 + 8 + g] = bi1;
        red[warp * 8 + g] = (fn0 - 2.f * best0) + (fn1 - 2.f * best1);
    }
    __syncthreads();

    // deterministic block reduce of 64 partials
    if (tid < 32) {
        float v = red[tid] + red[tid + 32];
        v += __shfl_down_sync(0xffffffffu, v, 16);
        v += __shfl_down_sync(0xffffffffu, v, 8);
        v += __shfl_down_sync(0xffffffffu, v, 4);
        v += __shfl_down_sync(0xffffffffu, v, 2);
        v += __shfl_down_sync(0xffffffffu, v, 1);
        if (tid == 0) g_partial[blockIdx.x] = v;
    }

    // write q (exact fp32 codebook rows)
    for (int i = tid; i < 8192; i += 256) {
        int p = i & 127, d = i >> 7;
        int n = blockIdx.x * 128 + p;
        int bb = n / 900, sp = n - bb * 900;
        z[((size_t)(bb * 64 + d)) * 900 + sp] = cb[sidx[p] * 64 + d];
    }
}

// ======== conv5 (1x1, 32->64) as split-tf32 GEMM ========
__global__ void __launch_bounds__(256) c5_mma(const float* __restrict__ in,
                                              const float* __restrict__ w,
                                              const float* __restrict__ bias,
                                              float* __restrict__ out)
{
    __shared__ float Wh[32 * 72];
    __shared__ float Wl[32 * 72];
    __shared__ float sb[64];

    const int tid = threadIdx.x;
    for (int i = tid; i < 2048; i += 256) {
        int co = i >> 5, ci = i & 31;
        float v = w[i];
        float h = tf32r(v);
        Wh[ci * 72 + co] = h;
        Wl[ci * 72 + co] = tf32r(v - h);
    }
    if (tid < 64) sb[tid] = bias[tid];
    __syncthreads();

    const int lane = tid & 31, warp = tid >> 5;
    const int g = lane >> 2, t = lane & 3;
    const int p0 = blockIdx.x * 128 + warp * 16 + g;
    const int p1 = p0 + 8;
    const int b0 = p0 / 900, sp0 = p0 - b0 * 900;
    const int b1 = p1 / 900, sp1 = p1 - b1 * 900;

    uint32_t ah[4][4], al[4][4];
    #pragma unroll
    for (int ck = 0; ck < 4; ck++) {
        int d0 = ck * 8 + t, d1 = d0 + 4;
        float v0 = in[((size_t)(b0 * 32 + d0)) * 900 + sp0];
        float v1 = in[((size_t)(b1 * 32 + d0)) * 900 + sp1];
        float v2 = in[((size_t)(b0 * 32 + d1)) * 900 + sp0];
        float v3 = in[((size_t)(b1 * 32 + d1)) * 900 + sp1];
        float h;
        h = tf32r(v0); ah[ck][0] = __float_as_uint(h); al[ck][0] = __float_as_uint(tf32r(v0 - h));
        h = tf32r(v1); ah[ck][1] = __float_as_uint(h); al[ck][1] = __float_as_uint(tf32r(v1 - h));
        h = tf32r(v2); ah[ck][2] = __float_as_uint(h); al[ck][2] = __float_as_uint(tf32r(v2 - h));
        h = tf32r(v3); ah[ck][3] = __float_as_uint(h); al[ck][3] = __float_as_uint(tf32r(v3 - h));
    }

    #pragma unroll
    for (int tile = 0; tile < 8; tile++) {
        float c[4] = {0.f, 0.f, 0.f, 0.f};
        #pragma unroll
        for (int ck = 0; ck < 4; ck++) {
            int k0 = ck * 8 + t;
            uint32_t b0h = __float_as_uint(Wh[k0 * 72 + tile * 8 + g]);
            uint32_t b1h = __float_as_uint(Wh[(k0 + 4) * 72 + tile * 8 + g]);
            uint32_t b0l = __float_as_uint(Wl[k0 * 72 + tile * 8 + g]);
            uint32_t b1l = __float_as_uint(Wl[(k0 + 4) * 72 + tile * 8 + g]);
            MMA_TF32(c, ah[ck][0], ah[ck][1], ah[ck][2], ah[ck][3], b0h, b1h);
            MMA_TF32(c, ah[ck][0], ah[ck][1], ah[ck][2], ah[ck][3], b0l, b1l);
            MMA_TF32(c, al[ck][0], al[ck][1], al[ck][2], al[ck][3], b0h, b1h);
        }
        int co0 = tile * 8 + 2 * t;
        float v;
        v = c[0] + sb[co0];     v = v >= 0.f ? v : LRELU_SLOPE * v;
        out[((size_t)(b0 * 64 + co0)) * 900 + sp0] = v;
        v = c[1] + sb[co0 + 1]; v = v >= 0.f ? v : LRELU_SLOPE * v;
        out[((size_t)(b0 * 64 + co0 + 1)) * 900 + sp0] = v;
        v = c[2] + sb[co0];     v = v >= 0.f ? v : LRELU_SLOPE * v;
        out[((size_t)(b1 * 64 + co0)) * 900 + sp1] = v;
        v = c[3] + sb[co0 + 1]; v = v >= 0.f ? v : LRELU_SLOPE * v;
        out[((size_t)(b1 * 64 + co0 + 1)) * 900 + sp1] = v;
    }
}

// ---------------- deterministic loss finalize (450 partials) ----------------
__global__ void loss_fin(float* __restrict__ out, int out_size)
{
    __shared__ float red[256];
    float v = 0.f;
    if (threadIdx.x < 450) v = g_partial[threadIdx.x];
    if (threadIdx.x + 256 < 450) v += g_partial[threadIdx.x + 256];
    red[threadIdx.x] = v;
    __syncthreads();
    for (int s = 128; s > 0; s >>= 1) {
        if (threadIdx.x < s) red[threadIdx.x] += red[threadIdx.x + s];
        __syncthreads();
    }
    if (threadIdx.x == 0)
        out[out_size - 1] = 1.25f * red[0] / 3686400.0f;
}

// ---------------- weight preps ----------------
__global__ void wprep_d1(const float* __restrict__ w, float* __restrict__ wT)
{
    int i = blockIdx.x * 256 + threadIdx.x;
    if (i >= 18432) return;
    int tap = i / 2048;
    int r   = i - tap * 2048;
    int ci  = r >> 5, co = r & 31;
    wT[i] = tf32r(w[((size_t)co * 64 + ci) * 9 + tap]);
}

template<int CIN, int COUT>
__global__ void wprep_tc(const float* __restrict__ w, float* __restrict__ dst)
{
    int i = blockIdx.x * 256 + threadIdx.x;
    if (i >= 16 * CIN * COUT) return;
    int co = i % COUT;
    int ci = (i / COUT) % CIN;
    int dk = (i / (COUT * CIN)) % 4;
    int cls = i / (COUT * CIN * 4);
    int hp = cls >> 1, wp = cls & 1;
    int dkh = dk >> 1, dkw = dk & 1;
    dst[i] = tf32r(w[((size_t)ci * COUT + co) * 16 + (hp + 2 * dkh) * 4 + (wp + 2 * dkw)]);
}

// ============== d1: 3x3 conv 64->32 pad1 via tf32 MMA ==============
__global__ void __launch_bounds__(256)
d1_mma(const float* __restrict__ in, const float* __restrict__ wT,
       const float* __restrict__ bias, float* __restrict__ out)
{
    __shared__ float As[64 * 33];
    __shared__ float Bs[64 * 136];

    const int oh0 = blockIdx.x * 2;
    const int b   = blockIdx.y;
    const int tid = threadIdx.x;

    const float* ib = in + (size_t)b * 64 * 900;
    for (int i = tid; i < 8704; i += 256) {
        int ci = i / 136; int rem = i - ci * 136;
        int r4 = rem / 34; int j = rem - r4 * 34;
        int ih = oh0 - 1 + r4; int iw = j - 1;
        float v = 0.f;
        if ((unsigned)ih < 30u && (unsigned)iw < 30u) v = ib[ci * 900 + ih * 30 + iw];
        Bs[i] = tf32r(v);
    }

    const int lane = tid & 31, warp = tid >> 5;
    const int mq = warp & 1, nw = warp >> 1;
    const int g = lane >> 2, t = lane & 3;
    const int rW = nw >> 1;
    const int owb = (nw & 1) * 16;

    float c0[4] = {0.f, 0.f, 0.f, 0.f};
    float c1[4] = {0.f, 0.f, 0.f, 0.f};

    for (int tap = 0; tap < 9; tap++) {
        __syncthreads();
        const float* wsrc = wT + tap * 2048;
        for (int i = tid; i < 2048; i += 256)
            As[(i >> 5) * 33 + (i & 31)] = wsrc[i];
        __syncthreads();

        int kh = tap / 3, kw = tap - kh * 3;
        int boff = (rW + kh) * 34 + owb + g + kw;

        #pragma unroll
        for (int ck = 0; ck < 8; ck++) {
            int k0 = ck * 8 + t;
            const float* wr = As + k0 * 33 + mq * 16 + g;
            uint32_t a0 = __float_as_uint(wr[0]);
            uint32_t a1 = __float_as_uint(wr[8]);
            uint32_t a2 = __float_as_uint(wr[4 * 33]);
            uint32_t a3 = __float_as_uint(wr[4 * 33 + 8]);
            uint32_t b0 = __float_as_uint(Bs[k0 * 136 + boff]);
            uint32_t b1 = __float_as_uint(Bs[(k0 + 4) * 136 + boff]);
            MMA_TF32(c0, a0, a1, a2, a3, b0, b1);
            uint32_t b2 = __float_as_uint(Bs[k0 * 136 + boff + 8]);
            uint32_t b3 = __float_as_uint(Bs[(k0 + 4) * 136 + boff + 8]);
            MMA_TF32(c1, a0, a1, a2, a3, b2, b3);
        }
    }

    const int oh = oh0 + rW;
    #pragma unroll
    for (int nt = 0; nt < 2; nt++) {
        const float* cc = nt ? c1 : c0;
        #pragma unroll
        for (int half = 0; half < 2; half++) {
            int co = mq * 16 + g + half * 8;
            float bia = bias[co];
            #pragma unroll
            for (int x = 0; x < 2; x++) {
                int ow = owb + nt * 8 + 2 * t + x;
                if (ow < 30) {
                    float v = cc[half * 2 + x] + bia;
                    v = v >= 0.f ? v : LRELU_SLOPE * v;
                    out[(((size_t)b * 32 + co) * 30 + oh) * 30 + ow] = v;
                }
            }
        }
    }
}

// ====== tconv k4 s2 via parity classes, tf32 MMA ======
template<int CIN, int COUT, int RSTRIP, int JW, int NMT, int NT>
__global__ void __launch_bounds__(256)
tconv_mma(const float* __restrict__ in, const float* __restrict__ wc,
          const float* __restrict__ bias, float* __restrict__ out,
          int HIN, int WIN, int HOUT, int WOUT)
{
    constexpr int KK = 4 * CIN;
    constexpr int CP = COUT + 1;
    constexpr int ISTR = (RSTRIP + 1) * JW;
    constexpr int KSPD = CIN / 8;

    __shared__ float Ws[KK * CP];
    __shared__ float Is[CIN * ISTR];

    const int b = blockIdx.z;
    const int cls = blockIdx.y;
    const int hp = cls >> 1, wp = cls & 1;
    const int NOHH = (HOUT - hp + 1) >> 1;
    const int NOWW = (WOUT - wp + 1) >> 1;
    const int ohh0 = blockIdx.x * RSTRIP;
    const int tid = threadIdx.x;

    const float* wsrc = wc + (size_t)cls * KK * COUT;
    for (int i = tid; i < KK * COUT; i += 256) {
        int k = i / COUT, co = i - k * COUT;
        Ws[k * CP + co] = wsrc[i];
    }
    const float* ibp = in + (size_t)b * CIN * HIN * WIN;
    for (int i = tid; i < CIN * ISTR; i += 256) {
        int ci = i / ISTR; int rem = i - ci * ISTR;
        int rr = rem / JW; int jj = rem - rr * JW;
        int ih = ohh0 - 1 + rr; int iw = jj - 1;
        float v = 0.f;
        if ((unsigned)ih < (unsigned)HIN && (unsigned)iw < (unsigned)WIN)
            v = ibp[ci * HIN * WIN + ih * WIN + iw];
        Is[i] = tf32r(v);
    }
    __syncthreads();

    const int lane = tid & 31, warp = tid >> 5;
    const int g = lane >> 2, t = lane & 3;
    const int MPOS = RSTRIP * NOWW;

    int rA[NMT], oA[NMT], rB[NMT], oB[NMT];
    bool vA[NMT], vB[NMT];
    #pragma unroll
    for (int i = 0; i < NMT; i++) {
        int mt = warp + i * 8;
        int m0 = mt * 16 + g, m1 = m0 + 8;
        int r0 = m0 / NOWW, o0 = m0 - r0 * NOWW;
        int r1 = m1 / NOWW, o1 = m1 - r1 * NOWW;
        vA[i] = (m0 < MPOS) && (ohh0 + r0 < NOHH);
        vB[i] = (m1 < MPOS) && (ohh0 + r1 < NOHH);
        if (m0 >= MPOS) { r0 = 0; o0 = 0; }
        if (m1 >= MPOS) { r1 = 0; o1 = 0; }
        rA[i] = r0; oA[i] = o0; rB[i] = r1; oB[i] = o1;
    }

    float acc[NMT][NT][4];
    #pragma unroll
    for (int i = 0; i < NMT; i++)
        #pragma unroll
        for (int nt = 0; nt < NT; nt++)
            #pragma unroll
            for (int x = 0; x < 4; x++) acc[i][nt][x] = 0.f;

    #pragma unroll
    for (int ck = 0; ck < KK / 8; ck++) {
        int dk = ck / KSPD;
        int dkh = dk >> 1, dkw = dk & 1;
        int k0 = ck * 8 + t;
        int ci0 = k0 - dk * CIN;
        uint32_t bw0[NT], bw1[NT];
        #pragma unroll
        for (int nt = 0; nt < NT; nt++) {
            bw0[nt] = __float_as_uint(Ws[k0 * CP + nt * 8 + g]);
            bw1[nt] = __float_as_uint(Ws[(k0 + 4) * CP + nt * 8 + g]);
        }
        int roff = (1 - dkh) * JW + (1 - dkw);
        #pragma unroll
        for (int i = 0; i < NMT; i++) {
            const float* p0 = Is + ci0 * ISTR + rA[i] * JW + oA[i] + roff;
            const float* p1 = Is + ci0 * ISTR + rB[i] * JW + oB[i] + roff;
            uint32_t a0 = __float_as_uint(p0[0]);
            uint32_t a1 = __float_as_uint(p1[0]);
            uint32_t a2 = __float_as_uint(p0[4 * ISTR]);
            uint32_t a3 = __float_as_uint(p1[4 * ISTR]);
            #pragma unroll
            for (int nt = 0; nt < NT; nt++)
                MMA_TF32(acc[i][nt], a0, a1, a2, a3, bw0[nt], bw1[nt]);
        }
    }

    #pragma unroll
    for (int i = 0; i < NMT; i++) {
        #pragma unroll
        for (int nt = 0; nt < NT; nt++) {
            #pragma unroll
            for (int x = 0; x < 2; x++) {
                int co = nt * 8 + 2 * t + x;
                float bia = bias[co];
                if (vA[i]) {
                    int oh = 2 * (ohh0 + rA[i]) + hp;
                    int ow = 2 * oA[i] + wp;
                    float v = acc[i][nt][x] + bia;
                    v = v >= 0.f ? v : LRELU_SLOPE * v;
                    out[(((size_t)b * COUT + co) * HOUT + oh) * WOUT + ow] = v;
                }
                if (vB[i]) {
                    int oh = 2 * (ohh0 + rB[i]) + hp;
                    int ow = 2 * oB[i] + wp;
                    float v = acc[i][nt][2 + x] + bia;
                    v = v >= 0.f ? v : LRELU_SLOPE * v;
                    out[(((size_t)b * COUT + co) * HOUT + oh) * WOUT + ow] = v;
                }
            }
        }
    }
}

// ---------------- launch ----------------
extern "C" void kernel_launch(void* const* d_in, const int* in_sizes, int n_in,
                              void* d_out, int out_size)
{
    (void)in_sizes; (void)n_in;
    const float* x   = (const float*)d_in[0];
    const float* ew1 = (const float*)d_in[1];  const float* eb1 = (const float*)d_in[2];
    const float* ew2 = (const float*)d_in[3];  const float* eb2 = (const float*)d_in[4];
    const float* ew3 = (const float*)d_in[5];  const float* eb3 = (const float*)d_in[6];
    const float* ew4 = (const float*)d_in[7];  const float* eb4 = (const float*)d_in[8];
    const float* ew5 = (const float*)d_in[9];  const float* eb5 = (const float*)d_in[10];
    const float* dw1 = (const float*)d_in[11]; const float* db1 = (const float*)d_in[12];
    const float* dw2 = (const float*)d_in[13]; const float* db2 = (const float*)d_in[14];
    const float* dw3 = (const float*)d_in[15]; const float* db3 = (const float*)d_in[16];
    const float* dw4 = (const float*)d_in[17]; const float* db4 = (const float*)d_in[18];
    const float* cbk = (const float*)d_in[19];
    float* out = (float*)d_out;

    float *bufA, *bufB, *wT, *wT2, *wT3;
    cudaGetSymbolAddress((void**)&bufA, g_bufA);
    cudaGetSymbolAddress((void**)&bufB, g_bufB);
    cudaGetSymbolAddress((void**)&wT,   g_wT);
    cudaGetSymbolAddress((void**)&wT2,  g_wT2);
    cudaGetSymbolAddress((void**)&wT3,  g_wT3);

    const int B = 64;

    // weight preps (independent)
    wprep_d1<<<72, 256>>>(dw1, wT);
    wprep_tc<32, 16><<<32, 256>>>(dw2, wT2);
    wprep_tc<16, 8><<<8, 256>>>(dw3, wT3);
    cnorm_k<<<2, 256>>>(cbk);

    // ---- encoder ----
    conv_t2<1, 8, 8, 4, 2, 0, 4, 1><<<dim3(32, 1, B), 128>>>(x, ew1, eb1, bufA, 256, 256, 127, 127, 32);
    conv_t2<8, 16, 16, 4, 2, 0, 2, 1><<<dim3(16, 1, B), 128>>>(bufA, ew2, eb2, bufB, 127, 127, 62, 62, 31);
    conv_t2<16, 32, 8, 4, 2, 0, 5, 1><<<dim3(2, 4, B), 96>>>(bufB, ew3, eb3, bufA, 62, 62, 30, 30, 6);
    conv_t2<32, 32, 8, 3, 1, 1, 5, 1><<<dim3(2, 4, B), 96>>>(bufA, ew4, eb4, bufB, 30, 30, 30, 30, 6);
    // conv5 as split-tf32 GEMM: bufB -> bufA
    c5_mma<<<450, 256>>>(bufB, ew5, eb5, bufA);

    // ---- VQ (split-tf32 MMA, argmin-preserving) ----
    vq_mma<<<450, 256>>>(bufA, cbk, bufB);

    // ---- decoder (tf32 MMA) ----
    d1_mma<<<dim3(15, 64), 256>>>(bufB, wT, db1, bufA);
    tconv_mma<32, 16, 8, 33, 2, 2><<<dim3(4, 4, B), 256>>>(bufA, wT2, db2, bufB, 30, 30, 63, 63);
    tconv_mma<16, 8, 8, 66, 5, 1><<<dim3(9, 4, B), 256>>>(bufB, wT3, db3, bufA, 63, 63, 129, 129);
    tconv_t2<8, 1, 1, 8, 2><<<dim3(68, 1, B), 128>>>(bufA, dw4, db4, out, 129, 129, 260, 260, 33);

    // ---- loss scalar ----
    loss_fin<<<1, 256>>>(out, out_size);
}